// round 3
// baseline (speedup 1.0000x reference)
#include <cuda_runtime.h>
#include <math.h>

#define N_NODES 50000
#define DH      256
#define NG      64
#define DH4     (DH/4)
#define MAX_E   600000

// ---------------- scratch (static device globals; no runtime allocation) ----
__device__ __align__(16) float g_G[N_NODES * DH];   // H_in @ W
__device__ __align__(16) float g_M[N_NODES * DH];   // aggregation accumulator
__device__ __align__(16) float g_H[N_NODES * DH];   // relu(M + b) -> next layer input
__device__ float g_deg[N_NODES];
__device__ float g_dinv[N_NODES];
__device__ __align__(16) float g_pool[NG * DH];
__device__ float g_cnt[NG];
__device__ int   g_src[MAX_E];
__device__ int   g_dst[MAX_E];
__device__ int   g_batch[N_NODES];
__device__ int   g_is64;

// ---------------- index dtype detection + conversion ------------------------
// If the buffer holds int64 of small non-negative values, every odd 32-bit
// word is zero. For int32 random node ids, essentially never.
__global__ void k_detect(const unsigned int* __restrict__ ei_words) {
    if (threadIdx.x == 0) {
        int nz = 0;
        for (int i = 0; i < 128; i++) nz += (ei_words[2 * i + 1] != 0u);
        g_is64 = (nz == 0) ? 1 : 0;
    }
}

__global__ void k_convert(const unsigned int* __restrict__ ei_words,
                          const unsigned int* __restrict__ batch_words, int E) {
    int t = blockIdx.x * blockDim.x + threadIdx.x;
    int is64 = g_is64;
    if (t < E) {
        if (is64) {
            g_src[t] = (int)ei_words[2 * t];
            g_dst[t] = (int)ei_words[2 * (E + t)];
        } else {
            g_src[t] = (int)ei_words[t];
            g_dst[t] = (int)ei_words[E + t];
        }
    }
    if (t < N_NODES) {
        g_batch[t] = is64 ? (int)batch_words[2 * t] : (int)batch_words[t];
    }
}

// ---------------- degree / normalization ------------------------------------
__global__ void k_deg_init() {
    int i = blockIdx.x * blockDim.x + threadIdx.x;
    if (i < N_NODES) g_deg[i] = 1.0f;   // self loop
}

__global__ void k_deg_count(int E) {
    int e = blockIdx.x * blockDim.x + threadIdx.x;
    if (e < E) atomicAdd(&g_deg[g_dst[e]], 1.0f);
}

__global__ void k_dinv() {
    int i = blockIdx.x * blockDim.x + threadIdx.x;
    if (i < N_NODES) g_dinv[i] = rsqrtf(g_deg[i]);
}

// ---------------- SGEMM: C = A @ B, plus M = dinv[row]^2 * C  ----------------
#define BM 128
#define BN 128
#define BK 8
#define TM 8
#define TN 8

__global__ __launch_bounds__(256) void k_sgemm(int K, const float* __restrict__ Aopt,
                                               const float* __restrict__ B) {
    const float* A = Aopt ? Aopt : g_H;

    __shared__ float As[BK][BM];
    __shared__ float Bs[BK][BN];

    const int tid  = threadIdx.x;          // 0..255
    const int cCol = blockIdx.x;           // 0..1
    const int cRow = blockIdx.y;           // 0..390

    const int tRow = (tid / (BN / TN)) * TM;
    const int tCol = (tid % (BN / TN)) * TN;

    const int aRow = tid / (BK / 4);
    const int aCol = (tid % (BK / 4)) * 4;
    const int bRow = tid / (BN / 4);
    const int bCol = (tid % (BN / 4)) * 4;

    const int rowBase = cRow * BM;

    float acc[TM][TN];
    #pragma unroll
    for (int i = 0; i < TM; i++)
        #pragma unroll
        for (int j = 0; j < TN; j++) acc[i][j] = 0.0f;

    float regA[TM], regB[TN];

    for (int k0 = 0; k0 < K; k0 += BK) {
        {
            int gr = rowBase + aRow;
            float4 av = make_float4(0.f, 0.f, 0.f, 0.f);
            if (gr < N_NODES)
                av = *(const float4*)(A + (size_t)gr * K + k0 + aCol);
            As[aCol + 0][aRow] = av.x;
            As[aCol + 1][aRow] = av.y;
            As[aCol + 2][aRow] = av.z;
            As[aCol + 3][aRow] = av.w;
        }
        {
            float4 bv = *(const float4*)(B + (size_t)(k0 + bRow) * DH + cCol * BN + bCol);
            *(float4*)(&Bs[bRow][bCol]) = bv;
        }
        __syncthreads();

        #pragma unroll
        for (int kk = 0; kk < BK; kk++) {
            #pragma unroll
            for (int i = 0; i < TM; i++) regA[i] = As[kk][tRow + i];
            #pragma unroll
            for (int j = 0; j < TN; j++) regB[j] = Bs[kk][tCol + j];
            #pragma unroll
            for (int i = 0; i < TM; i++)
                #pragma unroll
                for (int j = 0; j < TN; j++)
                    acc[i][j] += regA[i] * regB[j];
        }
        __syncthreads();
    }

    // epilogue: write G, and M = dinv(row)^2 * G (the self-loop term)
    #pragma unroll
    for (int i = 0; i < TM; i++) {
        int gr = rowBase + tRow + i;
        if (gr >= N_NODES) continue;
        float s  = g_dinv[gr];
        float s2 = s * s;
        #pragma unroll
        for (int j = 0; j < TN; j += 4) {
            size_t off = (size_t)gr * DH + cCol * BN + tCol + j;
            float4 v = make_float4(acc[i][j], acc[i][j + 1], acc[i][j + 2], acc[i][j + 3]);
            *(float4*)(g_G + off) = v;
            float4 m = make_float4(v.x * s2, v.y * s2, v.z * s2, v.w * s2);
            *(float4*)(g_M + off) = m;
        }
    }
}

// ---------------- edge scatter: M[dst] += norm * G[src] ---------------------
// One warp per edge; each lane handles 8 floats (2 x float4 loads, 8 scalar REDs).
__global__ void k_scatter(int E) {
    int w    = (blockIdx.x * blockDim.x + threadIdx.x) >> 5;
    int lane = threadIdx.x & 31;
    if (w >= E) return;
    int s = g_src[w];
    int d = g_dst[w];
    float nw = __ldg(&g_dinv[s]) * __ldg(&g_dinv[d]);

    const float4* gp = (const float4*)g_G + (size_t)s * DH4;
    float*        mp = g_M + (size_t)d * DH;

    #pragma unroll
    for (int it = 0; it < 2; it++) {
        int j = lane + 32 * it;
        float4 v = __ldg(gp + j);
        atomicAdd(mp + 4 * j + 0, v.x * nw);
        atomicAdd(mp + 4 * j + 1, v.y * nw);
        atomicAdd(mp + 4 * j + 2, v.z * nw);
        atomicAdd(mp + 4 * j + 3, v.w * nw);
    }
}

// ---------------- H = relu(M + b) -------------------------------------------
__global__ void k_relu_bias(const float* __restrict__ b) {
    int t = blockIdx.x * blockDim.x + threadIdx.x;
    if (t >= N_NODES * DH4) return;
    int c = t & (DH4 - 1);
    float4 bb = __ldg((const float4*)b + c);
    float4 v  = ((const float4*)g_M)[t];
    v.x = fmaxf(v.x + bb.x, 0.f);
    v.y = fmaxf(v.y + bb.y, 0.f);
    v.z = fmaxf(v.z + bb.z, 0.f);
    v.w = fmaxf(v.w + bb.w, 0.f);
    ((float4*)g_H)[t] = v;
}

// ---------------- pooling -----------------------------------------------------
__global__ void k_pool_zero() {
    int t = blockIdx.x * blockDim.x + threadIdx.x;
    if (t < NG * DH) g_pool[t] = 0.0f;
    if (t < NG) g_cnt[t] = 0.0f;
}

__global__ void k_pool() {
    int t = blockIdx.x * blockDim.x + threadIdx.x;
    if (t >= N_NODES * DH4) return;
    int i = t >> 6;           // node  (DH4 == 64)
    int c = t & 63;           // float4 chunk
    int b = g_batch[i];
    float4 v = ((const float4*)g_H)[t];
    float* pp = g_pool + b * DH + 4 * c;
    atomicAdd(pp + 0, v.x);
    atomicAdd(pp + 1, v.y);
    atomicAdd(pp + 2, v.z);
    atomicAdd(pp + 3, v.w);
    if (c == 0) atomicAdd(&g_cnt[b], 1.0f);
}

// ---------------- classifier head ------------------------------------------
__global__ void k_classifier(const float* __restrict__ Wc1, const float* __restrict__ bc1,
                             const float* __restrict__ Wc2, const float* __restrict__ bc2,
                             float* __restrict__ out) {
    __shared__ float gr[DH];
    __shared__ float h1[DH];
    int b = blockIdx.x, tid = threadIdx.x;

    float invc = 1.0f / fmaxf(g_cnt[b], 1.0f);
    gr[tid] = g_pool[b * DH + tid] * invc;
    __syncthreads();

    float acc = bc1[tid];
    #pragma unroll 8
    for (int k = 0; k < DH; k++) acc += gr[k] * Wc1[k * DH + tid];
    h1[tid] = fmaxf(acc, 0.f);
    __syncthreads();

    if (tid < 5) {
        float o = bc2[tid];
        #pragma unroll 8
        for (int k = 0; k < DH; k++) o += h1[k] * Wc2[k * 5 + tid];
        out[b * 5 + tid] = o;
    }
}

// ---------------- launch ------------------------------------------------------
extern "C" void kernel_launch(void* const* d_in, const int* in_sizes, int n_in,
                              void* d_out, int out_size) {
    const float*        x     = (const float*)d_in[0];
    const unsigned int* ei    = (const unsigned int*)d_in[1];
    const unsigned int* batch = (const unsigned int*)d_in[2];
    const float* W0  = (const float*)d_in[3];
    const float* b0  = (const float*)d_in[4];
    const float* W1  = (const float*)d_in[5];
    const float* b1  = (const float*)d_in[6];
    const float* W2  = (const float*)d_in[7];
    const float* b2  = (const float*)d_in[8];
    const float* Wc1 = (const float*)d_in[9];
    const float* bc1 = (const float*)d_in[10];
    const float* Wc2 = (const float*)d_in[11];
    const float* bc2 = (const float*)d_in[12];
    float* out = (float*)d_out;

    const int E = in_sizes[1] / 2;   // element count of edge_index is 2*E

    // index dtype detection + unpack to int32
    k_detect<<<1, 32>>>(ei);
    k_convert<<<(E + 255) / 256, 256>>>(ei, batch, E);

    // normalization
    k_deg_init<<<(N_NODES + 255) / 256, 256>>>();
    k_deg_count<<<(E + 255) / 256, 256>>>(E);
    k_dinv<<<(N_NODES + 255) / 256, 256>>>();

    const dim3 ggrid(DH / BN, (N_NODES + BM - 1) / BM);   // (2, 391)
    const int  scatterBlocks = (E * 32 + 255) / 256;
    const int  ewBlocks      = (N_NODES * DH4 + 255) / 256;

    // layer 0 (K = 128, A = x)
    k_sgemm<<<ggrid, 256>>>(128, x, W0);
    k_scatter<<<scatterBlocks, 256>>>(E);
    k_relu_bias<<<ewBlocks, 256>>>(b0);

    // layer 1 (K = 256, A = g_H)
    k_sgemm<<<ggrid, 256>>>(256, nullptr, W1);
    k_scatter<<<scatterBlocks, 256>>>(E);
    k_relu_bias<<<ewBlocks, 256>>>(b1);

    // layer 2 (K = 256, A = g_H)
    k_sgemm<<<ggrid, 256>>>(256, nullptr, W2);
    k_scatter<<<scatterBlocks, 256>>>(E);
    k_relu_bias<<<ewBlocks, 256>>>(b2);

    // pooling + classifier
    k_pool_zero<<<(NG * DH + 255) / 256, 256>>>();
    k_pool<<<ewBlocks, 256>>>();
    k_classifier<<<NG, DH>>>(Wc1, bc1, Wc2, bc2, out);
}

// round 6
// speedup vs baseline: 1.7177x; 1.7177x over previous
#include <cuda_runtime.h>
#include <math.h>

#define N_NODES 50000
#define DH      256
#define NG      64
#define DH4     (DH/4)
#define MAX_E   600000

// ---------------- scratch (static device globals; no runtime allocation) ----
__device__ __align__(16) float g_G[N_NODES * DH];   // H_in @ W
__device__ __align__(16) float g_H[N_NODES * DH];   // relu(agg + b)
__device__ float g_dinv[N_NODES];
__device__ __align__(16) float g_pool[NG * DH];
__device__ float g_cnt[NG];
__device__ int   g_src[MAX_E];
__device__ int   g_dst[MAX_E];
__device__ int   g_batch[N_NODES];
__device__ int   g_is64;
// CSR (dst-indexed)
__device__ int   g_degi[N_NODES];
__device__ int   g_rowptr[N_NODES + 1];
__device__ int   g_cursor[N_NODES];
__device__ int   g_col[MAX_E];      // src of each edge, grouped by dst
__device__ float g_w[MAX_E];        // dinv[src]*dinv[dst]

// ---------------- index dtype detection + conversion ------------------------
__global__ void k_detect(const unsigned int* __restrict__ ei_words) {
    if (threadIdx.x == 0) {
        int nz = 0;
        for (int i = 0; i < 128; i++) nz += (ei_words[2 * i + 1] != 0u);
        g_is64 = (nz == 0) ? 1 : 0;
    }
}

__global__ void k_convert(const unsigned int* __restrict__ ei_words,
                          const unsigned int* __restrict__ batch_words, int E) {
    int t = blockIdx.x * blockDim.x + threadIdx.x;
    int is64 = g_is64;
    if (t < E) {
        if (is64) {
            g_src[t] = (int)ei_words[2 * t];
            g_dst[t] = (int)ei_words[2 * (E + t)];
        } else {
            g_src[t] = (int)ei_words[t];
            g_dst[t] = (int)ei_words[E + t];
        }
    }
    if (t < N_NODES) {
        g_batch[t] = is64 ? (int)batch_words[2 * t] : (int)batch_words[t];
    }
}

// ---------------- CSR build ---------------------------------------------------
// IMPORTANT: must cover N_NODES threads (zeroing degi/cursor every call).
__global__ void k_zero() {
    int t = blockIdx.x * blockDim.x + threadIdx.x;
    if (t < N_NODES) { g_degi[t] = 0; g_cursor[t] = 0; }
    if (t < NG * DH) g_pool[t] = 0.0f;
    if (t < NG) g_cnt[t] = 0.0f;
}

__global__ void k_count(int E) {
    int e = blockIdx.x * blockDim.x + threadIdx.x;
    if (e < E) atomicAdd(&g_degi[g_dst[e]], 1);
}

// single-block exclusive scan over degrees; also dinv = rsqrt(deg_in + 1)
__global__ void k_scan() {
    __shared__ int buf[1024];
    __shared__ int carry;
    int tid = threadIdx.x;
    if (tid == 0) carry = 0;
    __syncthreads();
    for (int base = 0; base < N_NODES; base += 1024) {
        int idx = base + tid;
        int v = (idx < N_NODES) ? g_degi[idx] : 0;
        buf[tid] = v;
        __syncthreads();
        for (int off = 1; off < 1024; off <<= 1) {
            int t = (tid >= off) ? buf[tid - off] : 0;
            __syncthreads();
            buf[tid] += t;
            __syncthreads();
        }
        if (idx < N_NODES) {
            g_rowptr[idx] = carry + buf[tid] - v;   // exclusive
            g_dinv[idx]   = rsqrtf((float)(v + 1)); // + self loop
        }
        __syncthreads();
        if (tid == 1023) carry += buf[1023];
        __syncthreads();
    }
    if (tid == 0) g_rowptr[N_NODES] = carry;
}

__global__ void k_fill(int E) {
    int e = blockIdx.x * blockDim.x + threadIdx.x;
    if (e >= E) return;
    int s = g_src[e], d = g_dst[e];
    int pos = g_rowptr[d] + atomicAdd(&g_cursor[d], 1);
    g_col[pos] = s;
    g_w[pos]   = g_dinv[s] * g_dinv[d];
}

__global__ void k_batchcnt() {
    int i = blockIdx.x * blockDim.x + threadIdx.x;
    if (i < N_NODES) atomicAdd(&g_cnt[g_batch[i]], 1.0f);
}

// ---------------- SGEMM: g_G = A @ B ----------------------------------------
#define BM 128
#define BN 128
#define BK 8
#define TM 8
#define TN 8

__global__ __launch_bounds__(256) void k_sgemm(int K, const float* __restrict__ Aopt,
                                               const float* __restrict__ B) {
    const float* A = Aopt ? Aopt : g_H;

    __shared__ float As[BK][BM];
    __shared__ float Bs[BK][BN];

    const int tid  = threadIdx.x;
    const int cCol = blockIdx.x;
    const int cRow = blockIdx.y;

    const int tRow = (tid / (BN / TN)) * TM;
    const int tCol = (tid % (BN / TN)) * TN;

    const int aRow = tid / (BK / 4);
    const int aCol = (tid % (BK / 4)) * 4;
    const int bRow = tid / (BN / 4);
    const int bCol = (tid % (BN / 4)) * 4;

    const int rowBase = cRow * BM;

    float acc[TM][TN];
    #pragma unroll
    for (int i = 0; i < TM; i++)
        #pragma unroll
        for (int j = 0; j < TN; j++) acc[i][j] = 0.0f;

    float regA[TM], regB[TN];

    for (int k0 = 0; k0 < K; k0 += BK) {
        {
            int gr = rowBase + aRow;
            float4 av = make_float4(0.f, 0.f, 0.f, 0.f);
            if (gr < N_NODES)
                av = *(const float4*)(A + (size_t)gr * K + k0 + aCol);
            As[aCol + 0][aRow] = av.x;
            As[aCol + 1][aRow] = av.y;
            As[aCol + 2][aRow] = av.z;
            As[aCol + 3][aRow] = av.w;
        }
        {
            float4 bv = *(const float4*)(B + (size_t)(k0 + bRow) * DH + cCol * BN + bCol);
            *(float4*)(&Bs[bRow][bCol]) = bv;
        }
        __syncthreads();

        #pragma unroll
        for (int kk = 0; kk < BK; kk++) {
            #pragma unroll
            for (int i = 0; i < TM; i++) regA[i] = As[kk][tRow + i];
            #pragma unroll
            for (int j = 0; j < TN; j++) regB[j] = Bs[kk][tCol + j];
            #pragma unroll
            for (int i = 0; i < TM; i++)
                #pragma unroll
                for (int j = 0; j < TN; j++)
                    acc[i][j] += regA[i] * regB[j];
        }
        __syncthreads();
    }

    #pragma unroll
    for (int i = 0; i < TM; i++) {
        int gr = rowBase + tRow + i;
        if (gr >= N_NODES) continue;
        #pragma unroll
        for (int j = 0; j < TN; j += 4) {
            size_t off = (size_t)gr * DH + cCol * BN + tCol + j;
            *(float4*)(g_G + off) =
                make_float4(acc[i][j], acc[i][j + 1], acc[i][j + 2], acc[i][j + 3]);
        }
    }
}

// ---------------- gather aggregation + bias + relu ---------------------------
// one warp per dst node; each lane owns 8 features (2 x float4)
__global__ __launch_bounds__(256) void k_aggregate(const float* __restrict__ bias) {
    int node = (blockIdx.x * blockDim.x + threadIdx.x) >> 5;
    int lane = threadIdx.x & 31;
    if (node >= N_NODES) return;

    const float4* Gi = (const float4*)g_G + (size_t)node * DH4;
    float s  = g_dinv[node];
    float s2 = s * s;

    float4 a0 = __ldg(Gi + lane);
    float4 a1 = __ldg(Gi + lane + 32);
    a0.x *= s2; a0.y *= s2; a0.z *= s2; a0.w *= s2;
    a1.x *= s2; a1.y *= s2; a1.z *= s2; a1.w *= s2;

    int beg = g_rowptr[node];
    int end = g_rowptr[node + 1];

    int e = beg;
    for (; e + 1 < end; e += 2) {
        int   c0 = __ldg(&g_col[e]);
        int   c1 = __ldg(&g_col[e + 1]);
        float w0 = __ldg(&g_w[e]);
        float w1 = __ldg(&g_w[e + 1]);
        const float4* G0 = (const float4*)g_G + (size_t)c0 * DH4;
        const float4* G1 = (const float4*)g_G + (size_t)c1 * DH4;
        float4 v00 = __ldg(G0 + lane);
        float4 v01 = __ldg(G0 + lane + 32);
        float4 v10 = __ldg(G1 + lane);
        float4 v11 = __ldg(G1 + lane + 32);
        a0.x += w0 * v00.x; a0.y += w0 * v00.y; a0.z += w0 * v00.z; a0.w += w0 * v00.w;
        a1.x += w0 * v01.x; a1.y += w0 * v01.y; a1.z += w0 * v01.z; a1.w += w0 * v01.w;
        a0.x += w1 * v10.x; a0.y += w1 * v10.y; a0.z += w1 * v10.z; a0.w += w1 * v10.w;
        a1.x += w1 * v11.x; a1.y += w1 * v11.y; a1.z += w1 * v11.z; a1.w += w1 * v11.w;
    }
    if (e < end) {
        int   c = __ldg(&g_col[e]);
        float w = __ldg(&g_w[e]);
        const float4* Gs = (const float4*)g_G + (size_t)c * DH4;
        float4 v0 = __ldg(Gs + lane);
        float4 v1 = __ldg(Gs + lane + 32);
        a0.x += w * v0.x; a0.y += w * v0.y; a0.z += w * v0.z; a0.w += w * v0.w;
        a1.x += w * v1.x; a1.y += w * v1.y; a1.z += w * v1.z; a1.w += w * v1.w;
    }

    float4 b0 = __ldg((const float4*)bias + lane);
    float4 b1 = __ldg((const float4*)bias + lane + 32);
    a0.x = fmaxf(a0.x + b0.x, 0.f); a0.y = fmaxf(a0.y + b0.y, 0.f);
    a0.z = fmaxf(a0.z + b0.z, 0.f); a0.w = fmaxf(a0.w + b0.w, 0.f);
    a1.x = fmaxf(a1.x + b1.x, 0.f); a1.y = fmaxf(a1.y + b1.y, 0.f);
    a1.z = fmaxf(a1.z + b1.z, 0.f); a1.w = fmaxf(a1.w + b1.w, 0.f);

    float4* Hi = (float4*)g_H + (size_t)node * DH4;
    Hi[lane]      = a0;
    Hi[lane + 32] = a1;
}

// ---------------- pooling -----------------------------------------------------
__global__ void k_pool() {
    int t = blockIdx.x * blockDim.x + threadIdx.x;
    if (t >= N_NODES * DH4) return;
    int i = t >> 6;
    int c = t & 63;
    int b = g_batch[i];
    float4 v = ((const float4*)g_H)[t];
    float* pp = g_pool + b * DH + 4 * c;
    atomicAdd(pp + 0, v.x);
    atomicAdd(pp + 1, v.y);
    atomicAdd(pp + 2, v.z);
    atomicAdd(pp + 3, v.w);
}

// ---------------- classifier head ------------------------------------------
__global__ void k_classifier(const float* __restrict__ Wc1, const float* __restrict__ bc1,
                             const float* __restrict__ Wc2, const float* __restrict__ bc2,
                             float* __restrict__ out) {
    __shared__ float gr[DH];
    __shared__ float h1[DH];
    int b = blockIdx.x, tid = threadIdx.x;

    float invc = 1.0f / fmaxf(g_cnt[b], 1.0f);
    gr[tid] = g_pool[b * DH + tid] * invc;
    __syncthreads();

    float acc = bc1[tid];
    #pragma unroll 8
    for (int k = 0; k < DH; k++) acc += gr[k] * Wc1[k * DH + tid];
    h1[tid] = fmaxf(acc, 0.f);
    __syncthreads();

    if (tid < 5) {
        float o = bc2[tid];
        #pragma unroll 8
        for (int k = 0; k < DH; k++) o += h1[k] * Wc2[k * 5 + tid];
        out[b * 5 + tid] = o;
    }
}

// ---------------- launch ------------------------------------------------------
extern "C" void kernel_launch(void* const* d_in, const int* in_sizes, int n_in,
                              void* d_out, int out_size) {
    const float*        x     = (const float*)d_in[0];
    const unsigned int* ei    = (const unsigned int*)d_in[1];
    const unsigned int* batch = (const unsigned int*)d_in[2];
    const float* W0  = (const float*)d_in[3];
    const float* b0  = (const float*)d_in[4];
    const float* W1  = (const float*)d_in[5];
    const float* b1  = (const float*)d_in[6];
    const float* W2  = (const float*)d_in[7];
    const float* b2  = (const float*)d_in[8];
    const float* Wc1 = (const float*)d_in[9];
    const float* bc1 = (const float*)d_in[10];
    const float* Wc2 = (const float*)d_in[11];
    const float* bc2 = (const float*)d_in[12];
    float* out = (float*)d_out;

    const int E = in_sizes[1] / 2;

    // prep: indices + CSR + pool counts
    k_detect<<<1, 32>>>(ei);
    k_convert<<<(E + 255) / 256, 256>>>(ei, batch, E);
    k_zero<<<(N_NODES + 255) / 256, 256>>>();   // FIX: cover all N_NODES
    k_count<<<(E + 255) / 256, 256>>>(E);
    k_scan<<<1, 1024>>>();
    k_fill<<<(E + 255) / 256, 256>>>(E);
    k_batchcnt<<<(N_NODES + 255) / 256, 256>>>();

    const dim3 ggrid(DH / BN, (N_NODES + BM - 1) / BM);
    const int  aggBlocks = (N_NODES * 32 + 255) / 256;
    const int  ewBlocks  = (N_NODES * DH4 + 255) / 256;

    // layer 0 (K = 128, A = x)
    k_sgemm<<<ggrid, 256>>>(128, x, W0);
    k_aggregate<<<aggBlocks, 256>>>(b0);

    // layer 1 (K = 256, A = g_H)
    k_sgemm<<<ggrid, 256>>>(256, nullptr, W1);
    k_aggregate<<<aggBlocks, 256>>>(b1);

    // layer 2 (K = 256, A = g_H)
    k_sgemm<<<ggrid, 256>>>(256, nullptr, W2);
    k_aggregate<<<aggBlocks, 256>>>(b2);

    // pooling + classifier
    k_pool<<<ewBlocks, 256>>>();
    k_classifier<<<NG, DH>>>(Wc1, bc1, Wc2, bc2, out);
}

// round 12
// speedup vs baseline: 2.0354x; 1.1850x over previous
#include <cuda_runtime.h>
#include <cuda_bf16.h>
#include <math.h>
#include <stdint.h>

#define N_NODES 50000
#define DH      256
#define NG      64
#define DH4     (DH/4)
#define MAX_E   600000

// ---------------- scratch (static device globals; no runtime allocation) ----
__device__ __align__(16) float g_G[N_NODES * DH];   // H_in @ W (fp32)
__device__ __align__(16) float g_H[N_NODES * DH];   // relu(agg + b) fp32
__device__ __align__(16) __nv_bfloat16 g_Hh[N_NODES * DH];  // bf16 hi split of H
__device__ __align__(16) __nv_bfloat16 g_Hl[N_NODES * DH];  // bf16 lo split of H
__device__ __align__(16) __nv_bfloat16 g_xh[N_NODES * 128];
__device__ __align__(16) __nv_bfloat16 g_xl[N_NODES * 128];
__device__ __align__(16) __nv_bfloat16 g_Bh[DH * DH];       // W^T hi  [256, K]
__device__ __align__(16) __nv_bfloat16 g_Bl[DH * DH];       // W^T lo
__device__ float g_dinv[N_NODES];
__device__ __align__(16) float g_pool[NG * DH];
__device__ float g_cnt[NG];
__device__ int   g_src[MAX_E];
__device__ int   g_dst[MAX_E];
__device__ int   g_batch[N_NODES];
__device__ int   g_is64;
__device__ int   g_degi[N_NODES];
__device__ int   g_rowptr[N_NODES + 1];
__device__ int   g_cursor[N_NODES];
__device__ int   g_col[MAX_E];
__device__ float g_w[MAX_E];

// ---------------- helpers -----------------------------------------------------
static __device__ __forceinline__ uint32_t smem_u32(const void* p) {
    uint32_t r;
    asm("{ .reg .u64 t; cvta.to.shared.u64 t, %1; cvt.u32.u64 %0, t; }"
        : "=r"(r) : "l"(p));
    return r;
}
static __device__ __forceinline__ void ldm_x4(uint32_t* r, uint32_t addr) {
    asm volatile("ldmatrix.sync.aligned.m8n8.x4.shared.b16 {%0,%1,%2,%3}, [%4];"
                 : "=r"(r[0]), "=r"(r[1]), "=r"(r[2]), "=r"(r[3]) : "r"(addr));
}
static __device__ __forceinline__ void mma16816(float* c, const uint32_t* a,
                                                uint32_t b0, uint32_t b1) {
    asm volatile("mma.sync.aligned.m16n8k16.row.col.f32.bf16.bf16.f32 "
                 "{%0,%1,%2,%3}, {%4,%5,%6,%7}, {%8,%9}, {%0,%1,%2,%3};"
                 : "+f"(c[0]), "+f"(c[1]), "+f"(c[2]), "+f"(c[3])
                 : "r"(a[0]), "r"(a[1]), "r"(a[2]), "r"(a[3]), "r"(b0), "r"(b1));
}

// ---------------- index dtype detection + conversion ------------------------
__global__ void k_detect(const unsigned int* __restrict__ ei_words) {
    if (threadIdx.x == 0) {
        int nz = 0;
        for (int i = 0; i < 128; i++) nz += (ei_words[2 * i + 1] != 0u);
        g_is64 = (nz == 0) ? 1 : 0;
    }
}

__global__ void k_convert(const unsigned int* __restrict__ ei_words,
                          const unsigned int* __restrict__ batch_words, int E) {
    int t = blockIdx.x * blockDim.x + threadIdx.x;
    int is64 = g_is64;
    if (t < E) {
        if (is64) {
            g_src[t] = (int)ei_words[2 * t];
            g_dst[t] = (int)ei_words[2 * (E + t)];
        } else {
            g_src[t] = (int)ei_words[t];
            g_dst[t] = (int)ei_words[E + t];
        }
    }
    if (t < N_NODES) {
        g_batch[t] = is64 ? (int)batch_words[2 * t] : (int)batch_words[t];
    }
}

// ---------------- CSR build ---------------------------------------------------
__global__ void k_zero() {
    int t = blockIdx.x * blockDim.x + threadIdx.x;
    if (t < N_NODES) { g_degi[t] = 0; g_cursor[t] = 0; }
    if (t < NG * DH) g_pool[t] = 0.0f;
    if (t < NG) g_cnt[t] = 0.0f;
}

__global__ void k_count(int E) {
    int e = blockIdx.x * blockDim.x + threadIdx.x;
    if (e < E) atomicAdd(&g_degi[g_dst[e]], 1);
}

__global__ void k_scan() {
    __shared__ int buf[1024];
    __shared__ int carry;
    int tid = threadIdx.x;
    if (tid == 0) carry = 0;
    __syncthreads();
    for (int base = 0; base < N_NODES; base += 1024) {
        int idx = base + tid;
        int v = (idx < N_NODES) ? g_degi[idx] : 0;
        buf[tid] = v;
        __syncthreads();
        for (int off = 1; off < 1024; off <<= 1) {
            int t = (tid >= off) ? buf[tid - off] : 0;
            __syncthreads();
            buf[tid] += t;
            __syncthreads();
        }
        if (idx < N_NODES) {
            g_rowptr[idx] = carry + buf[tid] - v;
            g_dinv[idx]   = rsqrtf((float)(v + 1));
        }
        __syncthreads();
        if (tid == 1023) carry += buf[1023];
        __syncthreads();
    }
    if (tid == 0) g_rowptr[N_NODES] = carry;
}

__global__ void k_fill(int E) {
    int e = blockIdx.x * blockDim.x + threadIdx.x;
    if (e >= E) return;
    int s = g_src[e], d = g_dst[e];
    int pos = g_rowptr[d] + atomicAdd(&g_cursor[d], 1);
    g_col[pos] = s;
    g_w[pos]   = g_dinv[s] * g_dinv[d];
}

__global__ void k_batchcnt() {
    int i = blockIdx.x * blockDim.x + threadIdx.x;
    if (i < N_NODES) atomicAdd(&g_cnt[g_batch[i]], 1.0f);
}

// ---------------- fp32 -> bf16 hi/lo splits -----------------------------------
__global__ void k_splitX(const float* __restrict__ x) {
    int t = blockIdx.x * blockDim.x + threadIdx.x;
    if (t >= N_NODES * 128) return;
    float v = x[t];
    __nv_bfloat16 h = __float2bfloat16(v);
    g_xh[t] = h;
    g_xl[t] = __float2bfloat16(v - __bfloat162float(h));
}

// W [K, 256] -> g_Bh/g_Bl [256, K] (transposed, hi/lo)
__global__ void k_splitW(const float* __restrict__ W, int K) {
    int t = blockIdx.x * blockDim.x + threadIdx.x;
    if (t >= K * DH) return;
    int k = t / DH, n = t % DH;
    float v = W[t];
    __nv_bfloat16 h = __float2bfloat16(v);
    g_Bh[n * K + k] = h;
    g_Bl[n * K + k] = __float2bfloat16(v - __bfloat162float(h));
}

// ---------------- split-bf16 HMMA GEMM: g_G = A @ W --------------------------
// CTA: 128x128, 8 warps (4x2), warp tile 32x64, K chunks of 32.
// D = Ah*Bh + Ah*Bl + Al*Bh (fp32 accum).
#define KC      32
#define ASTRIDE 40   // 32 + 8 pad (bf16) -> conflict-free ldmatrix

__global__ __launch_bounds__(256) void k_mma(int K, int useX) {
    __shared__ __align__(16) __nv_bfloat16 sAh[128 * ASTRIDE];
    __shared__ __align__(16) __nv_bfloat16 sAl[128 * ASTRIDE];
    __shared__ __align__(16) __nv_bfloat16 sBh[128 * ASTRIDE];
    __shared__ __align__(16) __nv_bfloat16 sBl[128 * ASTRIDE];

    const __nv_bfloat16* __restrict__ Ah = useX ? g_xh : g_Hh;
    const __nv_bfloat16* __restrict__ Al = useX ? g_xl : g_Hl;

    const int tid = threadIdx.x, wid = tid >> 5, lane = tid & 31;
    const int warpRow = wid >> 1, warpCol = wid & 1;
    const int cCol = blockIdx.x;
    const int rowBase = blockIdx.y * 128;

    float acc[2][8][4];
    #pragma unroll
    for (int mi = 0; mi < 2; mi++)
        #pragma unroll
        for (int ni = 0; ni < 8; ni++)
            #pragma unroll
            for (int q = 0; q < 4; q++) acc[mi][ni][q] = 0.0f;

    const int ldRow = tid >> 1;            // 0..127
    const int ldCol = (tid & 1) * 16;      // 0 or 16

    for (int k0 = 0; k0 < K; k0 += KC) {
        // ---- load A tile (hi/lo), zero-fill rows past N_NODES
        {
            int grow = rowBase + ldRow;
            uint4 h0 = make_uint4(0,0,0,0), h1 = h0, l0 = h0, l1 = h0;
            if (grow < N_NODES) {
                const uint4* ph = (const uint4*)(Ah + (size_t)grow * K + k0 + ldCol);
                const uint4* pl = (const uint4*)(Al + (size_t)grow * K + k0 + ldCol);
                h0 = ph[0]; h1 = ph[1]; l0 = pl[0]; l1 = pl[1];
            }
            *(uint4*)(sAh + ldRow * ASTRIDE + ldCol)     = h0;
            *(uint4*)(sAh + ldRow * ASTRIDE + ldCol + 8) = h1;
            *(uint4*)(sAl + ldRow * ASTRIDE + ldCol)     = l0;
            *(uint4*)(sAl + ldRow * ASTRIDE + ldCol + 8) = l1;
        }
        // ---- load B tile (n-major W^T rows)
        {
            const uint4* qh = (const uint4*)(g_Bh + (size_t)(cCol * 128 + ldRow) * K + k0 + ldCol);
            const uint4* ql = (const uint4*)(g_Bl + (size_t)(cCol * 128 + ldRow) * K + k0 + ldCol);
            *(uint4*)(sBh + ldRow * ASTRIDE + ldCol)     = qh[0];
            *(uint4*)(sBh + ldRow * ASTRIDE + ldCol + 8) = qh[1];
            *(uint4*)(sBl + ldRow * ASTRIDE + ldCol)     = ql[0];
            *(uint4*)(sBl + ldRow * ASTRIDE + ldCol + 8) = ql[1];
        }
        __syncthreads();

        #pragma unroll
        for (int ks = 0; ks < 2; ks++) {
            uint32_t ah[2][4], al[2][4];
            #pragma unroll
            for (int mi = 0; mi < 2; mi++) {
                int r = warpRow * 32 + mi * 16 + (lane & 15);
                int c = ks * 16 + (lane >> 4) * 8;
                ldm_x4(ah[mi], smem_u32(sAh + r * ASTRIDE + c));
                ldm_x4(al[mi], smem_u32(sAl + r * ASTRIDE + c));
            }
            uint32_t bh[4][4], bl[4][4];
            #pragma unroll
            for (int nj = 0; nj < 4; nj++) {
                int n = warpCol * 64 + nj * 16 + (lane & 7) + ((lane >> 3) & 1) * 8;
                int c = ks * 16 + (lane >> 4) * 8;
                ldm_x4(bh[nj], smem_u32(sBh + n * ASTRIDE + c));
                ldm_x4(bl[nj], smem_u32(sBl + n * ASTRIDE + c));
            }
            #pragma unroll
            for (int mi = 0; mi < 2; mi++) {
                #pragma unroll
                for (int nj = 0; nj < 4; nj++) {
                    // x4 reg order: {b0(t0), b0(t1), b1(t0), b1(t1)}
                    mma16816(acc[mi][nj * 2],     ah[mi], bh[nj][0], bh[nj][2]);
                    mma16816(acc[mi][nj * 2 + 1], ah[mi], bh[nj][1], bh[nj][3]);
                    mma16816(acc[mi][nj * 2],     ah[mi], bl[nj][0], bl[nj][2]);
                    mma16816(acc[mi][nj * 2 + 1], ah[mi], bl[nj][1], bl[nj][3]);
                    mma16816(acc[mi][nj * 2],     al[mi], bh[nj][0], bh[nj][2]);
                    mma16816(acc[mi][nj * 2 + 1], al[mi], bh[nj][1], bh[nj][3]);
                }
            }
        }
        __syncthreads();
    }

    // ---- epilogue: write fp32 G
    #pragma unroll
    for (int mi = 0; mi < 2; mi++) {
        int r0 = rowBase + warpRow * 32 + mi * 16 + (lane >> 2);
        #pragma unroll
        for (int ni = 0; ni < 8; ni++) {
            int col = cCol * 128 + warpCol * 64 + ni * 8 + (lane & 3) * 2;
            if (r0 < N_NODES)
                *(float2*)(g_G + (size_t)r0 * DH + col) =
                    make_float2(acc[mi][ni][0], acc[mi][ni][1]);
            if (r0 + 8 < N_NODES)
                *(float2*)(g_G + (size_t)(r0 + 8) * DH + col) =
                    make_float2(acc[mi][ni][2], acc[mi][ni][3]);
        }
    }
}

// ---------------- gather aggregation + bias + relu + bf16 split --------------
static __device__ __forceinline__ void split4(float4 v, uint2& hi, uint2& lo) {
    __nv_bfloat162 hxy = __floats2bfloat162_rn(v.x, v.y);
    __nv_bfloat162 hzw = __floats2bfloat162_rn(v.z, v.w);
    float lx = v.x - __bfloat162float(hxy.x), ly = v.y - __bfloat162float(hxy.y);
    float lz = v.z - __bfloat162float(hzw.x), lw = v.w - __bfloat162float(hzw.y);
    __nv_bfloat162 lxy = __floats2bfloat162_rn(lx, ly);
    __nv_bfloat162 lzw = __floats2bfloat162_rn(lz, lw);
    hi.x = *(uint32_t*)&hxy; hi.y = *(uint32_t*)&hzw;
    lo.x = *(uint32_t*)&lxy; lo.y = *(uint32_t*)&lzw;
}

__global__ __launch_bounds__(256) void k_aggregate(const float* __restrict__ bias) {
    int node = (blockIdx.x * blockDim.x + threadIdx.x) >> 5;
    int lane = threadIdx.x & 31;
    if (node >= N_NODES) return;

    const float4* Gi = (const float4*)g_G + (size_t)node * DH4;
    float s  = g_dinv[node];
    float s2 = s * s;

    float4 a0 = __ldg(Gi + lane);
    float4 a1 = __ldg(Gi + lane + 32);
    a0.x *= s2; a0.y *= s2; a0.z *= s2; a0.w *= s2;
    a1.x *= s2; a1.y *= s2; a1.z *= s2; a1.w *= s2;

    int beg = g_rowptr[node];
    int end = g_rowptr[node + 1];

    int e = beg;
    for (; e + 1 < end; e += 2) {
        int   c0 = __ldg(&g_col[e]);
        int   c1 = __ldg(&g_col[e + 1]);
        float w0 = __ldg(&g_w[e]);
        float w1 = __ldg(&g_w[e + 1]);
        const float4* G0 = (const float4*)g_G + (size_t)c0 * DH4;
        const float4* G1 = (const float4*)g_G + (size_t)c1 * DH4;
        float4 v00 = __ldg(G0 + lane);
        float4 v01 = __ldg(G0 + lane + 32);
        float4 v10 = __ldg(G1 + lane);
        float4 v11 = __ldg(G1 + lane + 32);
        a0.x += w0 * v00.x; a0.y += w0 * v00.y; a0.z += w0 * v00.z; a0.w += w0 * v00.w;
        a1.x += w0 * v01.x; a1.y += w0 * v01.y; a1.z += w0 * v01.z; a1.w += w0 * v01.w;
        a0.x += w1 * v10.x; a0.y += w1 * v10.y; a0.z += w1 * v10.z; a0.w += w1 * v10.w;
        a1.x += w1 * v11.x; a1.y += w1 * v11.y; a1.z += w1 * v11.z; a1.w += w1 * v11.w;
    }
    if (e < end) {
        int   c = __ldg(&g_col[e]);
        float w = __ldg(&g_w[e]);
        const float4* Gs = (const float4*)g_G + (size_t)c * DH4;
        float4 v0 = __ldg(Gs + lane);
        float4 v1 = __ldg(Gs + lane + 32);
        a0.x += w * v0.x; a0.y += w * v0.y; a0.z += w * v0.z; a0.w += w * v0.w;
        a1.x += w * v1.x; a1.y += w * v1.y; a1.z += w * v1.z; a1.w += w * v1.w;
    }

    float4 b0 = __ldg((const float4*)bias + lane);
    float4 b1 = __ldg((const float4*)bias + lane + 32);
    a0.x = fmaxf(a0.x + b0.x, 0.f); a0.y = fmaxf(a0.y + b0.y, 0.f);
    a0.z = fmaxf(a0.z + b0.z, 0.f); a0.w = fmaxf(a0.w + b0.w, 0.f);
    a1.x = fmaxf(a1.x + b1.x, 0.f); a1.y = fmaxf(a1.y + b1.y, 0.f);
    a1.z = fmaxf(a1.z + b1.z, 0.f); a1.w = fmaxf(a1.w + b1.w, 0.f);

    float4* Hi = (float4*)g_H + (size_t)node * DH4;
    Hi[lane]      = a0;
    Hi[lane + 32] = a1;

    uint2 h0, l0, h1, l1;
    split4(a0, h0, l0);
    split4(a1, h1, l1);
    *(uint2*)(g_Hh + (size_t)node * DH + 4 * lane)        = h0;
    *(uint2*)(g_Hl + (size_t)node * DH + 4 * lane)        = l0;
    *(uint2*)(g_Hh + (size_t)node * DH + 4 * (lane + 32)) = h1;
    *(uint2*)(g_Hl + (size_t)node * DH + 4 * (lane + 32)) = l1;
}

// ---------------- pooling -----------------------------------------------------
__global__ void k_pool() {
    int t = blockIdx.x * blockDim.x + threadIdx.x;
    if (t >= N_NODES * DH4) return;
    int i = t >> 6;
    int c = t & 63;
    int b = g_batch[i];
    float4 v = ((const float4*)g_H)[t];
    float* pp = g_pool + b * DH + 4 * c;
    atomicAdd(pp + 0, v.x);
    atomicAdd(pp + 1, v.y);
    atomicAdd(pp + 2, v.z);
    atomicAdd(pp + 3, v.w);
}

// ---------------- classifier head ------------------------------------------
__global__ void k_classifier(const float* __restrict__ Wc1, const float* __restrict__ bc1,
                             const float* __restrict__ Wc2, const float* __restrict__ bc2,
                             float* __restrict__ out) {
    __shared__ float gr[DH];
    __shared__ float h1[DH];
    int b = blockIdx.x, tid = threadIdx.x;

    float invc = 1.0f / fmaxf(g_cnt[b], 1.0f);
    gr[tid] = g_pool[b * DH + tid] * invc;
    __syncthreads();

    float acc = bc1[tid];
    #pragma unroll 8
    for (int k = 0; k < DH; k++) acc += gr[k] * Wc1[k * DH + tid];
    h1[tid] = fmaxf(acc, 0.f);
    __syncthreads();

    if (tid < 5) {
        float o = bc2[tid];
        #pragma unroll 8
        for (int k = 0; k < DH; k++) o += h1[k] * Wc2[k * 5 + tid];
        out[b * 5 + tid] = o;
    }
}

// ---------------- launch ------------------------------------------------------
extern "C" void kernel_launch(void* const* d_in, const int* in_sizes, int n_in,
                              void* d_out, int out_size) {
    const float*        x     = (const float*)d_in[0];
    const unsigned int* ei    = (const unsigned int*)d_in[1];
    const unsigned int* batch = (const unsigned int*)d_in[2];
    const float* W0  = (const float*)d_in[3];
    const float* b0  = (const float*)d_in[4];
    const float* W1  = (const float*)d_in[5];
    const float* b1  = (const float*)d_in[6];
    const float* W2  = (const float*)d_in[7];
    const float* b2  = (const float*)d_in[8];
    const float* Wc1 = (const float*)d_in[9];
    const float* bc1 = (const float*)d_in[10];
    const float* Wc2 = (const float*)d_in[11];
    const float* bc2 = (const float*)d_in[12];
    float* out = (float*)d_out;

    const int E = in_sizes[1] / 2;

    // prep: indices + CSR + pool counts + x split
    k_detect<<<1, 32>>>(ei);
    k_convert<<<(E + 255) / 256, 256>>>(ei, batch, E);
    k_zero<<<(N_NODES + 255) / 256, 256>>>();
    k_count<<<(E + 255) / 256, 256>>>(E);
    k_scan<<<1, 1024>>>();
    k_fill<<<(E + 255) / 256, 256>>>(E);
    k_batchcnt<<<(N_NODES + 255) / 256, 256>>>();
    k_splitX<<<(N_NODES * 128 + 255) / 256, 256>>>(x);

    const dim3 ggrid(2, (N_NODES + 127) / 128);   // (2, 391)
    const int  aggBlocks = (N_NODES * 32 + 255) / 256;
    const int  ewBlocks  = (N_NODES * DH4 + 255) / 256;

    // layer 0 (K = 128, A = x splits)
    k_splitW<<<(128 * DH + 255) / 256, 256>>>(W0, 128);
    k_mma<<<ggrid, 256>>>(128, 1);
    k_aggregate<<<aggBlocks, 256>>>(b0);

    // layer 1 (K = 256, A = H splits)
    k_splitW<<<(256 * DH + 255) / 256, 256>>>(W1, 256);
    k_mma<<<ggrid, 256>>>(256, 0);
    k_aggregate<<<aggBlocks, 256>>>(b1);

    // layer 2 (K = 256, A = H splits)
    k_splitW<<<(256 * DH + 255) / 256, 256>>>(W2, 256);
    k_mma<<<ggrid, 256>>>(256, 0);
    k_aggregate<<<aggBlocks, 256>>>(b2);

    // pooling + classifier
    k_pool<<<ewBlocks, 256>>>();
    k_classifier<<<NG, DH>>>(Wc1, bc1, Wc2, bc2, out);
}

// round 13
// speedup vs baseline: 2.2239x; 1.0926x over previous
#include <cuda_runtime.h>
#include <cuda_bf16.h>
#include <math.h>
#include <stdint.h>

#define N_NODES 50000
#define DH      256
#define NG      64
#define DH4     (DH/4)
#define MAX_E   600000

// ---------------- scratch (static device globals; no runtime allocation) ----
__device__ __align__(16) float g_G[N_NODES * DH];
__device__ __align__(16) float g_H[N_NODES * DH];
__device__ __align__(16) __nv_bfloat16 g_Hh[N_NODES * DH];
__device__ __align__(16) __nv_bfloat16 g_Hl[N_NODES * DH];
__device__ __align__(16) __nv_bfloat16 g_xh[N_NODES * 128];
__device__ __align__(16) __nv_bfloat16 g_xl[N_NODES * 128];
__device__ __align__(16) __nv_bfloat16 g_Bh[3][DH * DH];   // W^T hi per layer
__device__ __align__(16) __nv_bfloat16 g_Bl[3][DH * DH];   // W^T lo per layer
__device__ float g_dinv[N_NODES];
__device__ __align__(16) float g_pool[NG * DH];
__device__ float g_cnt[NG];
__device__ int   g_src[MAX_E];
__device__ int   g_dst[MAX_E];
__device__ int   g_batch[N_NODES];
__device__ int   g_is64;
__device__ int   g_degi[N_NODES];
__device__ int   g_rowptr[N_NODES + 1];
__device__ int   g_cursor[N_NODES];
__device__ int   g_col[MAX_E];
__device__ float g_w[MAX_E];

// ---------------- helpers -----------------------------------------------------
static __device__ __forceinline__ uint32_t smem_u32(const void* p) {
    uint32_t r;
    asm("{ .reg .u64 t; cvta.to.shared.u64 t, %1; cvt.u32.u64 %0, t; }"
        : "=r"(r) : "l"(p));
    return r;
}
static __device__ __forceinline__ void ldm_x4(uint32_t* r, uint32_t addr) {
    asm volatile("ldmatrix.sync.aligned.m8n8.x4.shared.b16 {%0,%1,%2,%3}, [%4];"
                 : "=r"(r[0]), "=r"(r[1]), "=r"(r[2]), "=r"(r[3]) : "r"(addr));
}
static __device__ __forceinline__ void mma16816(float* c, const uint32_t* a,
                                                uint32_t b0, uint32_t b1) {
    asm volatile("mma.sync.aligned.m16n8k16.row.col.f32.bf16.bf16.f32 "
                 "{%0,%1,%2,%3}, {%4,%5,%6,%7}, {%8,%9}, {%0,%1,%2,%3};"
                 : "+f"(c[0]), "+f"(c[1]), "+f"(c[2]), "+f"(c[3])
                 : "r"(a[0]), "r"(a[1]), "r"(a[2]), "r"(a[3]), "r"(b0), "r"(b1));
}
static __device__ __forceinline__ void cp16(uint32_t dst, const void* src, uint32_t sz) {
    asm volatile("cp.async.cg.shared.global [%0], [%1], 16, %2;"
                 :: "r"(dst), "l"(src), "r"(sz) : "memory");
}
#define CP_COMMIT()  asm volatile("cp.async.commit_group;" ::: "memory")
#define CP_WAIT(n)   asm volatile("cp.async.wait_group %0;" :: "n"(n) : "memory")

// ---------------- index dtype detection + conversion ------------------------
__global__ void k_detect(const unsigned int* __restrict__ ei_words) {
    if (threadIdx.x == 0) {
        int nz = 0;
        for (int i = 0; i < 128; i++) nz += (ei_words[2 * i + 1] != 0u);
        g_is64 = (nz == 0) ? 1 : 0;
    }
}

__global__ void k_convert(const unsigned int* __restrict__ ei_words,
                          const unsigned int* __restrict__ batch_words, int E) {
    int t = blockIdx.x * blockDim.x + threadIdx.x;
    int is64 = g_is64;
    if (t < E) {
        if (is64) {
            g_src[t] = (int)ei_words[2 * t];
            g_dst[t] = (int)ei_words[2 * (E + t)];
        } else {
            g_src[t] = (int)ei_words[t];
            g_dst[t] = (int)ei_words[E + t];
        }
    }
    if (t < N_NODES) {
        g_batch[t] = is64 ? (int)batch_words[2 * t] : (int)batch_words[t];
    }
}

// ---------------- CSR build ---------------------------------------------------
__global__ void k_zero() {
    int t = blockIdx.x * blockDim.x + threadIdx.x;
    if (t < N_NODES) { g_degi[t] = 0; g_cursor[t] = 0; }
    if (t < NG * DH) g_pool[t] = 0.0f;
    if (t < NG) g_cnt[t] = 0.0f;
}

__global__ void k_count(int E) {
    int t = blockIdx.x * blockDim.x + threadIdx.x;
    if (t < E) atomicAdd(&g_degi[g_dst[t]], 1);
    if (t < N_NODES) atomicAdd(&g_cnt[g_batch[t]], 1.0f);
}

__global__ void k_scan() {
    __shared__ int buf[1024];
    __shared__ int carry;
    int tid = threadIdx.x;
    if (tid == 0) carry = 0;
    __syncthreads();
    for (int base = 0; base < N_NODES; base += 1024) {
        int idx = base + tid;
        int v = (idx < N_NODES) ? g_degi[idx] : 0;
        buf[tid] = v;
        __syncthreads();
        for (int off = 1; off < 1024; off <<= 1) {
            int t = (tid >= off) ? buf[tid - off] : 0;
            __syncthreads();
            buf[tid] += t;
            __syncthreads();
        }
        if (idx < N_NODES) {
            g_rowptr[idx] = carry + buf[tid] - v;
            g_dinv[idx]   = rsqrtf((float)(v + 1));
        }
        __syncthreads();
        if (tid == 1023) carry += buf[1023];
        __syncthreads();
    }
    if (tid == 0) g_rowptr[N_NODES] = carry;
}

__global__ void k_fill(int E) {
    int e = blockIdx.x * blockDim.x + threadIdx.x;
    if (e >= E) return;
    int s = g_src[e], d = g_dst[e];
    int pos = g_rowptr[d] + atomicAdd(&g_cursor[d], 1);
    g_col[pos] = s;
    g_w[pos]   = g_dinv[s] * g_dinv[d];
}

// ---------------- fp32 -> bf16 hi/lo splits -----------------------------------
__global__ void k_splitX(const float* __restrict__ x) {
    int t = blockIdx.x * blockDim.x + threadIdx.x;
    if (t >= N_NODES * 128) return;
    float v = x[t];
    __nv_bfloat16 h = __float2bfloat16(v);
    g_xh[t] = h;
    g_xl[t] = __float2bfloat16(v - __bfloat162float(h));
}

// all three weights -> transposed hi/lo in one launch
__global__ void k_splitW_all(const float* __restrict__ W0,
                             const float* __restrict__ W1,
                             const float* __restrict__ W2) {
    int t = blockIdx.x * blockDim.x + threadIdx.x;
    const int T0 = 128 * DH, T12 = DH * DH;
    float v; int layer, idx;
    if (t < T0) {
        layer = 0; int k = t / DH, n = t % DH;
        v = W0[t]; idx = n * 128 + k;
    } else if (t < T0 + T12) {
        layer = 1; int u = t - T0; int k = u / DH, n = u % DH;
        v = W1[u]; idx = n * 256 + k;
    } else if (t < T0 + 2 * T12) {
        layer = 2; int u = t - T0 - T12; int k = u / DH, n = u % DH;
        v = W2[u]; idx = n * 256 + k;
    } else return;
    __nv_bfloat16 h = __float2bfloat16(v);
    g_Bh[layer][idx] = h;
    g_Bl[layer][idx] = __float2bfloat16(v - __bfloat162float(h));
}

// ---------------- split-bf16 HMMA GEMM, 2-stage cp.async pipeline -------------
// CTA: 128x128, 8 warps (4x2), warp tile 32x64, K chunks of 32.
#define KC       32
#define ASTRIDE  40                       // elements; 80 B row pitch
#define BUF_ELEM (128 * ASTRIDE)          // 5120 bf16 = 10240 B
#define BUF_B    (BUF_ELEM * 2)
#define MMA_SMEM (2 * 4 * BUF_B)          // 81920 B

__global__ __launch_bounds__(256) void k_mma(int K, int useX, int layer) {
    extern __shared__ __nv_bfloat16 dsm[];
    const __nv_bfloat16* __restrict__ Ah = useX ? g_xh : g_Hh;
    const __nv_bfloat16* __restrict__ Al = useX ? g_xl : g_Hl;
    const __nv_bfloat16* __restrict__ Bh = g_Bh[layer];
    const __nv_bfloat16* __restrict__ Bl = g_Bl[layer];

    const int tid = threadIdx.x, wid = tid >> 5, lane = tid & 31;
    const int warpRow = wid >> 1, warpCol = wid & 1;
    const int cCol = blockIdx.x;
    const int rowBase = blockIdx.y * 128;
    const uint32_t sb = smem_u32(dsm);

    const int ldRow = tid >> 1;                 // 0..127
    const int grow  = rowBase + ldRow;
    const uint32_t asz = (grow < N_NODES) ? 16u : 0u;
    const size_t aOff = (size_t)(grow < N_NODES ? grow : 0) * K;
    const size_t bOff = (size_t)(cCol * 128 + ldRow) * K;
    const uint32_t dRowB = (uint32_t)ldRow * (ASTRIDE * 2);   // bytes

    const int nC = K / KC;

    // issue loads for chunk c into stage s
    auto issue = [&](int c, int s) {
        const int k0 = c * KC;
        const uint32_t base = sb + (uint32_t)(s * 4) * BUF_B + dRowB;
        #pragma unroll
        for (int q = 0; q < 2; q++) {
            const int col8 = ((tid & 1) * 2 + q) * 8;
            const uint32_t d = base + col8 * 2;
            cp16(d,             Ah + aOff + k0 + col8, asz);
            cp16(d + BUF_B,     Al + aOff + k0 + col8, asz);
            cp16(d + 2 * BUF_B, Bh + bOff + k0 + col8, 16u);
            cp16(d + 3 * BUF_B, Bl + bOff + k0 + col8, 16u);
        }
        CP_COMMIT();
    };

    float acc[2][8][4];
    #pragma unroll
    for (int mi = 0; mi < 2; mi++)
        #pragma unroll
        for (int ni = 0; ni < 8; ni++)
            #pragma unroll
            for (int q = 0; q < 4; q++) acc[mi][ni][q] = 0.0f;

    issue(0, 0);
    issue(1, 1);

    for (int c = 0; c < nC; c++) {
        const int s = c & 1;
        if (c + 1 < nC) CP_WAIT(1); else CP_WAIT(0);
        __syncthreads();

        const __nv_bfloat16* sAh = dsm + (s * 4 + 0) * BUF_ELEM;
        const __nv_bfloat16* sAl = dsm + (s * 4 + 1) * BUF_ELEM;
        const __nv_bfloat16* sBh = dsm + (s * 4 + 2) * BUF_ELEM;
        const __nv_bfloat16* sBl = dsm + (s * 4 + 3) * BUF_ELEM;

        #pragma unroll
        for (int ks = 0; ks < 2; ks++) {
            uint32_t ah[2][4], al[2][4];
            #pragma unroll
            for (int mi = 0; mi < 2; mi++) {
                int r = warpRow * 32 + mi * 16 + (lane & 15);
                int cc = ks * 16 + (lane >> 4) * 8;
                ldm_x4(ah[mi], smem_u32(sAh + r * ASTRIDE + cc));
                ldm_x4(al[mi], smem_u32(sAl + r * ASTRIDE + cc));
            }
            uint32_t bh[4][4], bl[4][4];
            #pragma unroll
            for (int nj = 0; nj < 4; nj++) {
                int n = warpCol * 64 + nj * 16 + (lane & 7) + ((lane >> 3) & 1) * 8;
                int cc = ks * 16 + (lane >> 4) * 8;
                ldm_x4(bh[nj], smem_u32(sBh + n * ASTRIDE + cc));
                ldm_x4(bl[nj], smem_u32(sBl + n * ASTRIDE + cc));
            }
            #pragma unroll
            for (int mi = 0; mi < 2; mi++) {
                #pragma unroll
                for (int nj = 0; nj < 4; nj++) {
                    mma16816(acc[mi][nj * 2],     ah[mi], bh[nj][0], bh[nj][2]);
                    mma16816(acc[mi][nj * 2 + 1], ah[mi], bh[nj][1], bh[nj][3]);
                    mma16816(acc[mi][nj * 2],     ah[mi], bl[nj][0], bl[nj][2]);
                    mma16816(acc[mi][nj * 2 + 1], ah[mi], bl[nj][1], bl[nj][3]);
                    mma16816(acc[mi][nj * 2],     al[mi], bh[nj][0], bh[nj][2]);
                    mma16816(acc[mi][nj * 2 + 1], al[mi], bh[nj][1], bh[nj][3]);
                }
            }
        }
        __syncthreads();
        if (c + 2 < nC) issue(c + 2, s);
    }

    // epilogue
    #pragma unroll
    for (int mi = 0; mi < 2; mi++) {
        int r0 = rowBase + warpRow * 32 + mi * 16 + (lane >> 2);
        #pragma unroll
        for (int ni = 0; ni < 8; ni++) {
            int col = cCol * 128 + warpCol * 64 + ni * 8 + (lane & 3) * 2;
            if (r0 < N_NODES)
                *(float2*)(g_G + (size_t)r0 * DH + col) =
                    make_float2(acc[mi][ni][0], acc[mi][ni][1]);
            if (r0 + 8 < N_NODES)
                *(float2*)(g_G + (size_t)(r0 + 8) * DH + col) =
                    make_float2(acc[mi][ni][2], acc[mi][ni][3]);
        }
    }
}

// ---------------- gather aggregation + bias + relu ----------------------------
static __device__ __forceinline__ void split4(float4 v, uint2& hi, uint2& lo) {
    __nv_bfloat162 hxy = __floats2bfloat162_rn(v.x, v.y);
    __nv_bfloat162 hzw = __floats2bfloat162_rn(v.z, v.w);
    float lx = v.x - __bfloat162float(hxy.x), ly = v.y - __bfloat162float(hxy.y);
    float lz = v.z - __bfloat162float(hzw.x), lw = v.w - __bfloat162float(hzw.y);
    __nv_bfloat162 lxy = __floats2bfloat162_rn(lx, ly);
    __nv_bfloat162 lzw = __floats2bfloat162_rn(lz, lw);
    hi.x = *(uint32_t*)&hxy; hi.y = *(uint32_t*)&hzw;
    lo.x = *(uint32_t*)&lxy; lo.y = *(uint32_t*)&lzw;
}

// mode 0: write H + splits (feeds next GEMM). mode 1: final layer — pool only.
__global__ __launch_bounds__(256) void k_aggregate(const float* __restrict__ bias,
                                                   int mode) {
    int node = (blockIdx.x * blockDim.x + threadIdx.x) >> 5;
    int lane = threadIdx.x & 31;
    if (node >= N_NODES) return;

    const float4* Gi = (const float4*)g_G + (size_t)node * DH4;
    float s  = g_dinv[node];
    float s2 = s * s;

    float4 a0 = __ldg(Gi + lane);
    float4 a1 = __ldg(Gi + lane + 32);
    a0.x *= s2; a0.y *= s2; a0.z *= s2; a0.w *= s2;
    a1.x *= s2; a1.y *= s2; a1.z *= s2; a1.w *= s2;

    int beg = g_rowptr[node];
    int end = g_rowptr[node + 1];

    int e = beg;
    for (; e + 1 < end; e += 2) {
        int   c0 = __ldg(&g_col[e]);
        int   c1 = __ldg(&g_col[e + 1]);
        float w0 = __ldg(&g_w[e]);
        float w1 = __ldg(&g_w[e + 1]);
        const float4* G0 = (const float4*)g_G + (size_t)c0 * DH4;
        const float4* G1 = (const float4*)g_G + (size_t)c1 * DH4;
        float4 v00 = __ldg(G0 + lane);
        float4 v01 = __ldg(G0 + lane + 32);
        float4 v10 = __ldg(G1 + lane);
        float4 v11 = __ldg(G1 + lane + 32);
        a0.x += w0 * v00.x; a0.y += w0 * v00.y; a0.z += w0 * v00.z; a0.w += w0 * v00.w;
        a1.x += w0 * v01.x; a1.y += w0 * v01.y; a1.z += w0 * v01.z; a1.w += w0 * v01.w;
        a0.x += w1 * v10.x; a0.y += w1 * v10.y; a0.z += w1 * v10.z; a0.w += w1 * v10.w;
        a1.x += w1 * v11.x; a1.y += w1 * v11.y; a1.z += w1 * v11.z; a1.w += w1 * v11.w;
    }
    if (e < end) {
        int   c = __ldg(&g_col[e]);
        float w = __ldg(&g_w[e]);
        const float4* Gs = (const float4*)g_G + (size_t)c * DH4;
        float4 v0 = __ldg(Gs + lane);
        float4 v1 = __ldg(Gs + lane + 32);
        a0.x += w * v0.x; a0.y += w * v0.y; a0.z += w * v0.z; a0.w += w * v0.w;
        a1.x += w * v1.x; a1.y += w * v1.y; a1.z += w * v1.z; a1.w += w * v1.w;
    }

    float4 b0 = __ldg((const float4*)bias + lane);
    float4 b1 = __ldg((const float4*)bias + lane + 32);
    a0.x = fmaxf(a0.x + b0.x, 0.f); a0.y = fmaxf(a0.y + b0.y, 0.f);
    a0.z = fmaxf(a0.z + b0.z, 0.f); a0.w = fmaxf(a0.w + b0.w, 0.f);
    a1.x = fmaxf(a1.x + b1.x, 0.f); a1.y = fmaxf(a1.y + b1.y, 0.f);
    a1.z = fmaxf(a1.z + b1.z, 0.f); a1.w = fmaxf(a1.w + b1.w, 0.f);

    if (mode == 0) {
        float4* Hi = (float4*)g_H + (size_t)node * DH4;
        Hi[lane]      = a0;
        Hi[lane + 32] = a1;
        uint2 h0, l0, h1, l1;
        split4(a0, h0, l0);
        split4(a1, h1, l1);
        *(uint2*)(g_Hh + (size_t)node * DH + 4 * lane)        = h0;
        *(uint2*)(g_Hl + (size_t)node * DH + 4 * lane)        = l0;
        *(uint2*)(g_Hh + (size_t)node * DH + 4 * (lane + 32)) = h1;
        *(uint2*)(g_Hl + (size_t)node * DH + 4 * (lane + 32)) = l1;
    } else {
        int b = g_batch[node];
        float* p0 = g_pool + b * DH + 4 * lane;
        float* p1 = g_pool + b * DH + 4 * (lane + 32);
        atomicAdd(p0 + 0, a0.x); atomicAdd(p0 + 1, a0.y);
        atomicAdd(p0 + 2, a0.z); atomicAdd(p0 + 3, a0.w);
        atomicAdd(p1 + 0, a1.x); atomicAdd(p1 + 1, a1.y);
        atomicAdd(p1 + 2, a1.z); atomicAdd(p1 + 3, a1.w);
    }
}

// ---------------- classifier head ------------------------------------------
__global__ void k_classifier(const float* __restrict__ Wc1, const float* __restrict__ bc1,
                             const float* __restrict__ Wc2, const float* __restrict__ bc2,
                             float* __restrict__ out) {
    __shared__ float gr[DH];
    __shared__ float h1[DH];
    int b = blockIdx.x, tid = threadIdx.x;

    float invc = 1.0f / fmaxf(g_cnt[b], 1.0f);
    gr[tid] = g_pool[b * DH + tid] * invc;
    __syncthreads();

    float acc = bc1[tid];
    #pragma unroll 8
    for (int k = 0; k < DH; k++) acc += gr[k] * Wc1[k * DH + tid];
    h1[tid] = fmaxf(acc, 0.f);
    __syncthreads();

    if (tid < 5) {
        float o = bc2[tid];
        #pragma unroll 8
        for (int k = 0; k < DH; k++) o += h1[k] * Wc2[k * 5 + tid];
        out[b * 5 + tid] = o;
    }
}

// ---------------- launch ------------------------------------------------------
extern "C" void kernel_launch(void* const* d_in, const int* in_sizes, int n_in,
                              void* d_out, int out_size) {
    const float*        x     = (const float*)d_in[0];
    const unsigned int* ei    = (const unsigned int*)d_in[1];
    const unsigned int* batch = (const unsigned int*)d_in[2];
    const float* W0  = (const float*)d_in[3];
    const float* b0  = (const float*)d_in[4];
    const float* W1  = (const float*)d_in[5];
    const float* b1  = (const float*)d_in[6];
    const float* W2  = (const float*)d_in[7];
    const float* b2  = (const float*)d_in[8];
    const float* Wc1 = (const float*)d_in[9];
    const float* bc1 = (const float*)d_in[10];
    const float* Wc2 = (const float*)d_in[11];
    const float* bc2 = (const float*)d_in[12];
    float* out = (float*)d_out;

    const int E = in_sizes[1] / 2;

    cudaFuncSetAttribute(k_mma, cudaFuncAttributeMaxDynamicSharedMemorySize, MMA_SMEM);

    // prep
    k_detect<<<1, 32>>>(ei);
    k_convert<<<(E + 255) / 256, 256>>>(ei, batch, E);
    k_zero<<<(N_NODES + 255) / 256, 256>>>();
    k_count<<<(E + 255) / 256, 256>>>(E);
    k_scan<<<1, 1024>>>();
    k_fill<<<(E + 255) / 256, 256>>>(E);
    k_splitX<<<(N_NODES * 128 + 255) / 256, 256>>>(x);
    k_splitW_all<<<(128 * DH + 2 * DH * DH + 255) / 256, 256>>>(W0, W1, W2);

    const dim3 ggrid(2, (N_NODES + 127) / 128);   // (2, 391)
    const int  aggBlocks = (N_NODES * 32 + 255) / 256;

    // layer 0 (K = 128, A = x splits)
    k_mma<<<ggrid, 256, MMA_SMEM>>>(128, 1, 0);
    k_aggregate<<<aggBlocks, 256>>>(b0, 0);

    // layer 1
    k_mma<<<ggrid, 256, MMA_SMEM>>>(256, 0, 1);
    k_aggregate<<<aggBlocks, 256>>>(b1, 0);

    // layer 2 (final: aggregate pools directly)
    k_mma<<<ggrid, 256, MMA_SMEM>>>(256, 0, 2);
    k_aggregate<<<aggBlocks, 256>>>(b2, 1);

    // classifier
    k_classifier<<<NG, DH>>>(Wc1, bc1, Wc2, bc2, out);
}

// round 16
// speedup vs baseline: 3.4230x; 1.5392x over previous
#include <cuda_runtime.h>
#include <cuda_bf16.h>
#include <math.h>
#include <stdint.h>

#define N_NODES 50000
#define DH      256
#define NG      64
#define DH4     (DH/4)
#define MAX_E   600000

// ---------------- scratch (static device globals; no runtime allocation) ----
__device__ __align__(16) float g_G[N_NODES * DH];
__device__ __align__(16) __nv_bfloat16 g_Hh[N_NODES * DH];
__device__ __align__(16) __nv_bfloat16 g_Hl[N_NODES * DH];
__device__ __align__(16) __nv_bfloat16 g_xh[N_NODES * 128];
__device__ __align__(16) __nv_bfloat16 g_xl[N_NODES * 128];
__device__ __align__(16) __nv_bfloat16 g_Bh[3][DH * DH];
__device__ __align__(16) __nv_bfloat16 g_Bl[3][DH * DH];
__device__ float g_dinv[N_NODES];
__device__ __align__(16) float g_pool[NG * DH];
__device__ float g_cnt[NG];
__device__ int   g_src[MAX_E];
__device__ int   g_dst[MAX_E];
__device__ int   g_batch[N_NODES];
__device__ int   g_is64;
__device__ int   g_degi[N_NODES];
__device__ int   g_rowptr[N_NODES + 1];
__device__ int   g_cursor[N_NODES];
__device__ int   g_col[MAX_E];
__device__ float g_w[MAX_E];

// ---------------- helpers -----------------------------------------------------
static __device__ __forceinline__ uint32_t smem_u32(const void* p) {
    uint32_t r;
    asm("{ .reg .u64 t; cvta.to.shared.u64 t, %1; cvt.u32.u64 %0, t; }"
        : "=r"(r) : "l"(p));
    return r;
}
static __device__ __forceinline__ void ldm_x4(uint32_t* r, uint32_t addr) {
    asm volatile("ldmatrix.sync.aligned.m8n8.x4.shared.b16 {%0,%1,%2,%3}, [%4];"
                 : "=r"(r[0]), "=r"(r[1]), "=r"(r[2]), "=r"(r[3]) : "r"(addr));
}
static __device__ __forceinline__ void mma16816(float* c, const uint32_t* a,
                                                uint32_t b0, uint32_t b1) {
    asm volatile("mma.sync.aligned.m16n8k16.row.col.f32.bf16.bf16.f32 "
                 "{%0,%1,%2,%3}, {%4,%5,%6,%7}, {%8,%9}, {%0,%1,%2,%3};"
                 : "+f"(c[0]), "+f"(c[1]), "+f"(c[2]), "+f"(c[3])
                 : "r"(a[0]), "r"(a[1]), "r"(a[2]), "r"(a[3]), "r"(b0), "r"(b1));
}
static __device__ __forceinline__ void cp16(uint32_t dst, const void* src, uint32_t sz) {
    asm volatile("cp.async.cg.shared.global [%0], [%1], 16, %2;"
                 :: "r"(dst), "l"(src), "r"(sz) : "memory");
}
#define CP_COMMIT()  asm volatile("cp.async.commit_group;" ::: "memory")
#define CP_WAIT(n)   asm volatile("cp.async.wait_group %0;" :: "n"(n) : "memory")

// ---------------- index dtype detection + conversion ------------------------
__global__ void k_detect(const unsigned int* __restrict__ ei_words) {
    if (threadIdx.x == 0) {
        int nz = 0;
        for (int i = 0; i < 128; i++) nz += (ei_words[2 * i + 1] != 0u);
        g_is64 = (nz == 0) ? 1 : 0;
    }
}

__global__ void k_convert(const unsigned int* __restrict__ ei_words,
                          const unsigned int* __restrict__ batch_words, int E) {
    int t = blockIdx.x * blockDim.x + threadIdx.x;
    int is64 = g_is64;
    if (t < E) {
        if (is64) {
            g_src[t] = (int)ei_words[2 * t];
            g_dst[t] = (int)ei_words[2 * (E + t)];
        } else {
            g_src[t] = (int)ei_words[t];
            g_dst[t] = (int)ei_words[E + t];
        }
    }
    if (t < N_NODES) {
        g_batch[t] = is64 ? (int)batch_words[2 * t] : (int)batch_words[t];
    }
}

// ---------------- CSR build ---------------------------------------------------
__global__ void k_zero() {
    int t = blockIdx.x * blockDim.x + threadIdx.x;
    if (t < N_NODES) { g_degi[t] = 0; g_cursor[t] = 0; }
    if (t < NG * DH) g_pool[t] = 0.0f;
}

__global__ void k_count(int E) {
    int t = blockIdx.x * blockDim.x + threadIdx.x;
    if (t < E) atomicAdd(&g_degi[g_dst[t]], 1);
}

// graph sizes from SORTED batch ids: 64 binary searches, 1 block
__global__ void k_graphcnt() {
    int b = threadIdx.x;
    if (b >= NG) return;
    auto lb = [&](int key) {
        int lo = 0, hi = N_NODES;
        while (lo < hi) { int m = (lo + hi) >> 1; if (g_batch[m] < key) lo = m + 1; else hi = m; }
        return lo;
    };
    g_cnt[b] = (float)(lb(b + 1) - lb(b));
}

// shuffle-based exclusive scan over degrees; dinv = rsqrt(deg_in + 1)
__global__ void k_scan() {
    __shared__ int wsum[32];
    int tid = threadIdx.x, lane = tid & 31, wid = tid >> 5;
    int carry = 0;
    for (int base = 0; base < N_NODES; base += 1024) {
        int idx = base + tid;
        int v = (idx < N_NODES) ? g_degi[idx] : 0;
        int s = v;
        #pragma unroll
        for (int o = 1; o < 32; o <<= 1) {
            int t = __shfl_up_sync(0xffffffffu, s, o);
            if (lane >= o) s += t;
        }
        if (lane == 31) wsum[wid] = s;
        __syncthreads();
        if (wid == 0) {
            int ws = wsum[lane];
            #pragma unroll
            for (int o = 1; o < 32; o <<= 1) {
                int t = __shfl_up_sync(0xffffffffu, ws, o);
                if (lane >= o) ws += t;
            }
            wsum[lane] = ws;
        }
        __syncthreads();
        int prefix = (wid > 0) ? wsum[wid - 1] : 0;
        int total  = wsum[31];
        if (idx < N_NODES) {
            g_rowptr[idx] = carry + prefix + s - v;   // exclusive
            g_dinv[idx]   = rsqrtf((float)(v + 1));
        }
        carry += total;
        __syncthreads();
    }
    if (tid == 0) g_rowptr[N_NODES] = carry;
}

__global__ void k_fill(int E) {
    int e = blockIdx.x * blockDim.x + threadIdx.x;
    if (e >= E) return;
    int s = g_src[e], d = g_dst[e];
    int pos = g_rowptr[d] + atomicAdd(&g_cursor[d], 1);
    g_col[pos] = s;
    g_w[pos]   = g_dinv[s] * g_dinv[d];
}

// ---------------- fp32 -> bf16 hi/lo splits -----------------------------------
__global__ void k_splitX(const float* __restrict__ x) {
    int t = blockIdx.x * blockDim.x + threadIdx.x;
    if (t >= N_NODES * 128) return;
    float v = x[t];
    __nv_bfloat16 h = __float2bfloat16(v);
    g_xh[t] = h;
    g_xl[t] = __float2bfloat16(v - __bfloat162float(h));
}

__global__ void k_splitW_all(const float* __restrict__ W0,
                             const float* __restrict__ W1,
                             const float* __restrict__ W2) {
    int t = blockIdx.x * blockDim.x + threadIdx.x;
    const int T0 = 128 * DH, T12 = DH * DH;
    float v; int layer, idx;
    if (t < T0) {
        layer = 0; int k = t / DH, n = t % DH;
        v = W0[t]; idx = n * 128 + k;
    } else if (t < T0 + T12) {
        layer = 1; int u = t - T0; int k = u / DH, n = u % DH;
        v = W1[u]; idx = n * 256 + k;
    } else if (t < T0 + 2 * T12) {
        layer = 2; int u = t - T0 - T12; int k = u / DH, n = u % DH;
        v = W2[u]; idx = n * 256 + k;
    } else return;
    __nv_bfloat16 h = __float2bfloat16(v);
    g_Bh[layer][idx] = h;
    g_Bl[layer][idx] = __float2bfloat16(v - __bfloat162float(h));
}

// ---------------- split-bf16 HMMA GEMM, 2-stage cp.async pipeline -------------
#define KC       32
#define ASTRIDE  40
#define BUF_ELEM (128 * ASTRIDE)
#define BUF_B    (BUF_ELEM * 2)
#define MMA_SMEM (2 * 4 * BUF_B)          // 81920 B

__global__ __launch_bounds__(256) void k_mma(int K, int useX, int layer) {
    extern __shared__ __nv_bfloat16 dsm[];
    const __nv_bfloat16* __restrict__ Ah = useX ? g_xh : g_Hh;
    const __nv_bfloat16* __restrict__ Al = useX ? g_xl : g_Hl;
    const __nv_bfloat16* __restrict__ Bh = g_Bh[layer];
    const __nv_bfloat16* __restrict__ Bl = g_Bl[layer];

    const int tid = threadIdx.x, wid = tid >> 5, lane = tid & 31;
    const int warpRow = wid >> 1, warpCol = wid & 1;
    const int cCol = blockIdx.x;
    const int rowBase = blockIdx.y * 128;
    const uint32_t sb = smem_u32(dsm);

    const int ldRow = tid >> 1;
    const int grow  = rowBase + ldRow;
    const uint32_t asz = (grow < N_NODES) ? 16u : 0u;
    const size_t aOff = (size_t)(grow < N_NODES ? grow : 0) * K;
    const size_t bOff = (size_t)(cCol * 128 + ldRow) * K;
    const uint32_t dRowB = (uint32_t)ldRow * (ASTRIDE * 2);

    const int nC = K / KC;

    auto issue = [&](int c, int s) {
        const int k0 = c * KC;
        const uint32_t base = sb + (uint32_t)(s * 4) * BUF_B + dRowB;
        #pragma unroll
        for (int q = 0; q < 2; q++) {
            const int col8 = ((tid & 1) * 2 + q) * 8;
            const uint32_t d = base + col8 * 2;
            cp16(d,             Ah + aOff + k0 + col8, asz);
            cp16(d + BUF_B,     Al + aOff + k0 + col8, asz);
            cp16(d + 2 * BUF_B, Bh + bOff + k0 + col8, 16u);
            cp16(d + 3 * BUF_B, Bl + bOff + k0 + col8, 16u);
        }
        CP_COMMIT();
    };

    float acc[2][8][4];
    #pragma unroll
    for (int mi = 0; mi < 2; mi++)
        #pragma unroll
        for (int ni = 0; ni < 8; ni++)
            #pragma unroll
            for (int q = 0; q < 4; q++) acc[mi][ni][q] = 0.0f;

    issue(0, 0);
    issue(1, 1);

    for (int c = 0; c < nC; c++) {
        const int s = c & 1;
        if (c + 1 < nC) CP_WAIT(1); else CP_WAIT(0);
        __syncthreads();

        const __nv_bfloat16* sAh = dsm + (s * 4 + 0) * BUF_ELEM;
        const __nv_bfloat16* sAl = dsm + (s * 4 + 1) * BUF_ELEM;
        const __nv_bfloat16* sBh = dsm + (s * 4 + 2) * BUF_ELEM;
        const __nv_bfloat16* sBl = dsm + (s * 4 + 3) * BUF_ELEM;

        #pragma unroll
        for (int ks = 0; ks < 2; ks++) {
            uint32_t ah[2][4], al[2][4];
            #pragma unroll
            for (int mi = 0; mi < 2; mi++) {
                int r = warpRow * 32 + mi * 16 + (lane & 15);
                int cc = ks * 16 + (lane >> 4) * 8;
                ldm_x4(ah[mi], smem_u32(sAh + r * ASTRIDE + cc));
                ldm_x4(al[mi], smem_u32(sAl + r * ASTRIDE + cc));
            }
            uint32_t bh[4][4], bl[4][4];
            #pragma unroll
            for (int nj = 0; nj < 4; nj++) {
                int n = warpCol * 64 + nj * 16 + (lane & 7) + ((lane >> 3) & 1) * 8;
                int cc = ks * 16 + (lane >> 4) * 8;
                ldm_x4(bh[nj], smem_u32(sBh + n * ASTRIDE + cc));
                ldm_x4(bl[nj], smem_u32(sBl + n * ASTRIDE + cc));
            }
            #pragma unroll
            for (int mi = 0; mi < 2; mi++) {
                #pragma unroll
                for (int nj = 0; nj < 4; nj++) {
                    mma16816(acc[mi][nj * 2],     ah[mi], bh[nj][0], bh[nj][2]);
                    mma16816(acc[mi][nj * 2 + 1], ah[mi], bh[nj][1], bh[nj][3]);
                    mma16816(acc[mi][nj * 2],     ah[mi], bl[nj][0], bl[nj][2]);
                    mma16816(acc[mi][nj * 2 + 1], ah[mi], bl[nj][1], bl[nj][3]);
                    mma16816(acc[mi][nj * 2],     al[mi], bh[nj][0], bh[nj][2]);
                    mma16816(acc[mi][nj * 2 + 1], al[mi], bh[nj][1], bh[nj][3]);
                }
            }
        }
        __syncthreads();
        if (c + 2 < nC) issue(c + 2, s);
    }

    #pragma unroll
    for (int mi = 0; mi < 2; mi++) {
        int r0 = rowBase + warpRow * 32 + mi * 16 + (lane >> 2);
        #pragma unroll
        for (int ni = 0; ni < 8; ni++) {
            int col = cCol * 128 + warpCol * 64 + ni * 8 + (lane & 3) * 2;
            if (r0 < N_NODES)
                *(float2*)(g_G + (size_t)r0 * DH + col) =
                    make_float2(acc[mi][ni][0], acc[mi][ni][1]);
            if (r0 + 8 < N_NODES)
                *(float2*)(g_G + (size_t)(r0 + 8) * DH + col) =
                    make_float2(acc[mi][ni][2], acc[mi][ni][3]);
        }
    }
}

// ---------------- gather aggregation + bias + relu ----------------------------
static __device__ __forceinline__ void split4(float4 v, uint2& hi, uint2& lo) {
    __nv_bfloat162 hxy = __floats2bfloat162_rn(v.x, v.y);
    __nv_bfloat162 hzw = __floats2bfloat162_rn(v.z, v.w);
    float lx = v.x - __bfloat162float(hxy.x), ly = v.y - __bfloat162float(hxy.y);
    float lz = v.z - __bfloat162float(hzw.x), lw = v.w - __bfloat162float(hzw.y);
    __nv_bfloat162 lxy = __floats2bfloat162_rn(lx, ly);
    __nv_bfloat162 lzw = __floats2bfloat162_rn(lz, lw);
    hi.x = *(uint32_t*)&hxy; hi.y = *(uint32_t*)&hzw;
    lo.x = *(uint32_t*)&lxy; lo.y = *(uint32_t*)&lzw;
}

// mode 0: write bf16 splits (feeds next GEMM). mode 1: final layer — pool via smem.
// 8 warps per block = 8 nodes; N_NODES % 8 == 0 (50000/8 = 6250 blocks exact).
__global__ __launch_bounds__(256) void k_aggregate(const float* __restrict__ bias,
                                                   int mode) {
    __shared__ float sp[8 * DH];
    __shared__ int   sbatch[8];

    int node = (blockIdx.x * blockDim.x + threadIdx.x) >> 5;
    int lane = threadIdx.x & 31;
    int wid  = (threadIdx.x >> 5);
    bool valid = (node < N_NODES);

    float4 a0 = make_float4(0.f, 0.f, 0.f, 0.f), a1 = a0;

    if (valid) {
        const float4* Gi = (const float4*)g_G + (size_t)node * DH4;
        float s  = g_dinv[node];
        float s2 = s * s;

        a0 = __ldg(Gi + lane);
        a1 = __ldg(Gi + lane + 32);
        a0.x *= s2; a0.y *= s2; a0.z *= s2; a0.w *= s2;
        a1.x *= s2; a1.y *= s2; a1.z *= s2; a1.w *= s2;

        int beg = g_rowptr[node];
        int end = g_rowptr[node + 1];

        int e = beg;
        for (; e + 1 < end; e += 2) {
            int   c0 = __ldg(&g_col[e]);
            int   c1 = __ldg(&g_col[e + 1]);
            float w0 = __ldg(&g_w[e]);
            float w1 = __ldg(&g_w[e + 1]);
            const float4* G0 = (const float4*)g_G + (size_t)c0 * DH4;
            const float4* G1 = (const float4*)g_G + (size_t)c1 * DH4;
            float4 v00 = __ldg(G0 + lane);
            float4 v01 = __ldg(G0 + lane + 32);
            float4 v10 = __ldg(G1 + lane);
            float4 v11 = __ldg(G1 + lane + 32);
            a0.x += w0 * v00.x; a0.y += w0 * v00.y; a0.z += w0 * v00.z; a0.w += w0 * v00.w;
            a1.x += w0 * v01.x; a1.y += w0 * v01.y; a1.z += w0 * v01.z; a1.w += w0 * v01.w;
            a0.x += w1 * v10.x; a0.y += w1 * v10.y; a0.z += w1 * v10.z; a0.w += w1 * v10.w;
            a1.x += w1 * v11.x; a1.y += w1 * v11.y; a1.z += w1 * v11.z; a1.w += w1 * v11.w;
        }
        if (e < end) {
            int   c = __ldg(&g_col[e]);
            float w = __ldg(&g_w[e]);
            const float4* Gs = (const float4*)g_G + (size_t)c * DH4;
            float4 v0 = __ldg(Gs + lane);
            float4 v1 = __ldg(Gs + lane + 32);
            a0.x += w * v0.x; a0.y += w * v0.y; a0.z += w * v0.z; a0.w += w * v0.w;
            a1.x += w * v1.x; a1.y += w * v1.y; a1.z += w * v1.z; a1.w += w * v1.w;
        }

        float4 b0 = __ldg((const float4*)bias + lane);
        float4 b1 = __ldg((const float4*)bias + lane + 32);
        a0.x = fmaxf(a0.x + b0.x, 0.f); a0.y = fmaxf(a0.y + b0.y, 0.f);
        a0.z = fmaxf(a0.z + b0.z, 0.f); a0.w = fmaxf(a0.w + b0.w, 0.f);
        a1.x = fmaxf(a1.x + b1.x, 0.f); a1.y = fmaxf(a1.y + b1.y, 0.f);
        a1.z = fmaxf(a1.z + b1.z, 0.f); a1.w = fmaxf(a1.w + b1.w, 0.f);
    }

    if (mode == 0) {
        if (valid) {
            uint2 h0, l0, h1, l1;
            split4(a0, h0, l0);
            split4(a1, h1, l1);
            *(uint2*)(g_Hh + (size_t)node * DH + 4 * lane)        = h0;
            *(uint2*)(g_Hl + (size_t)node * DH + 4 * lane)        = l0;
            *(uint2*)(g_Hh + (size_t)node * DH + 4 * (lane + 32)) = h1;
            *(uint2*)(g_Hl + (size_t)node * DH + 4 * (lane + 32)) = l1;
        }
    } else {
        // block-level pooling: stage 8 node-vectors in smem, group by batch id
        *(float4*)(sp + wid * DH + 4 * lane)         = a0;
        *(float4*)(sp + wid * DH + 4 * (lane + 32))  = a1;
        if (lane == 0) sbatch[wid] = valid ? g_batch[node] : -1;
        __syncthreads();

        int f = threadIdx.x;   // 0..255 = feature
        float acc = 0.0f;
        int cb = sbatch[0];
        #pragma unroll
        for (int w = 0; w < 8; w++) {
            int bw = sbatch[w];
            if (bw != cb) {
                if (cb >= 0) atomicAdd(&g_pool[cb * DH + f], acc);
                acc = 0.0f; cb = bw;
            }
            acc += sp[w * DH + f];
        }
        if (cb >= 0) atomicAdd(&g_pool[cb * DH + f], acc);
    }
}

// ---------------- classifier head ------------------------------------------
__global__ void k_classifier(const float* __restrict__ Wc1, const float* __restrict__ bc1,
                             const float* __restrict__ Wc2, const float* __restrict__ bc2,
                             float* __restrict__ out) {
    __shared__ float gr[DH];
    __shared__ float h1[DH];
    int b = blockIdx.x, tid = threadIdx.x;

    float invc = 1.0f / fmaxf(g_cnt[b], 1.0f);
    gr[tid] = g_pool[b * DH + tid] * invc;
    __syncthreads();

    float acc = bc1[tid];
    #pragma unroll 8
    for (int k = 0; k < DH; k++) acc += gr[k] * Wc1[k * DH + tid];
    h1[tid] = fmaxf(acc, 0.f);
    __syncthreads();

    if (tid < 5) {
        float o = bc2[tid];
        #pragma unroll 8
        for (int k = 0; k < DH; k++) o += h1[k] * Wc2[k * 5 + tid];
        out[b * 5 + tid] = o;
    }
}

// ---------------- launch ------------------------------------------------------
extern "C" void kernel_launch(void* const* d_in, const int* in_sizes, int n_in,
                              void* d_out, int out_size) {
    const float*        x     = (const float*)d_in[0];
    const unsigned int* ei    = (const unsigned int*)d_in[1];
    const unsigned int* batch = (const unsigned int*)d_in[2];
    const float* W0  = (const float*)d_in[3];
    const float* b0  = (const float*)d_in[4];
    const float* W1  = (const float*)d_in[5];
    const float* b1  = (const float*)d_in[6];
    const float* W2  = (const float*)d_in[7];
    const float* b2  = (const float*)d_in[8];
    const float* Wc1 = (const float*)d_in[9];
    const float* bc1 = (const float*)d_in[10];
    const float* Wc2 = (const float*)d_in[11];
    const float* bc2 = (const float*)d_in[12];
    float* out = (float*)d_out;

    const int E = in_sizes[1] / 2;

    cudaFuncSetAttribute(k_mma, cudaFuncAttributeMaxDynamicSharedMemorySize, MMA_SMEM);

    // prep
    k_detect<<<1, 32>>>(ei);
    k_convert<<<(E + 255) / 256, 256>>>(ei, batch, E);
    k_zero<<<(N_NODES + 255) / 256, 256>>>();
    k_count<<<(E + 255) / 256, 256>>>(E);
    k_graphcnt<<<1, 64>>>();
    k_scan<<<1, 1024>>>();
    k_fill<<<(E + 255) / 256, 256>>>(E);
    k_splitX<<<(N_NODES * 128 + 255) / 256, 256>>>(x);
    k_splitW_all<<<(128 * DH + 2 * DH * DH + 255) / 256, 256>>>(W0, W1, W2);

    const dim3 ggrid(2, (N_NODES + 127) / 128);
    const int  aggBlocks = (N_NODES * 32 + 255) / 256;

    // layer 0 (K = 128, A = x splits)
    k_mma<<<ggrid, 256, MMA_SMEM>>>(128, 1, 0);
    k_aggregate<<<aggBlocks, 256>>>(b0, 0);

    // layer 1
    k_mma<<<ggrid, 256, MMA_SMEM>>>(256, 0, 1);
    k_aggregate<<<aggBlocks, 256>>>(b1, 0);

    // layer 2 (final: aggregate pools via smem reduction)
    k_mma<<<ggrid, 256, MMA_SMEM>>>(256, 0, 2);
    k_aggregate<<<aggBlocks, 256>>>(b2, 1);

    // classifier
    k_classifier<<<NG, DH>>>(Wc1, bc1, Wc2, bc2, out);
}

// round 17
// speedup vs baseline: 3.9750x; 1.1612x over previous
#include <cuda_runtime.h>
#include <cuda_bf16.h>
#include <math.h>
#include <stdint.h>

#define N_NODES 50000
#define DH      256
#define NG      64
#define DH4     (DH/4)
#define MAX_E   600000

// ---------------- scratch (static device globals; no runtime allocation) ----
__device__ __align__(16) float g_H[N_NODES * DH];            // relu(M@W+b) fp32
__device__ __align__(16) __nv_bfloat16 g_Mh[N_NODES * DH];   // bf16 hi of aggregated M
__device__ __align__(16) __nv_bfloat16 g_Ml[N_NODES * DH];   // bf16 lo
__device__ __align__(16) __nv_bfloat16 g_xh[N_NODES * 128];  // layer-0 M splits (128d)
__device__ __align__(16) __nv_bfloat16 g_xl[N_NODES * 128];
__device__ __align__(16) __nv_bfloat16 g_Bh[3][DH * DH];
__device__ __align__(16) __nv_bfloat16 g_Bl[3][DH * DH];
__device__ float g_dinv[N_NODES];
__device__ __align__(16) float g_pool[NG * DH];
__device__ float g_cnt[NG];
__device__ int   g_src[MAX_E];
__device__ int   g_dst[MAX_E];
__device__ int   g_batch[N_NODES];
__device__ int   g_is64;
__device__ int   g_degi[N_NODES];
__device__ int   g_rowptr[N_NODES + 1];
__device__ int   g_cursor[N_NODES];
__device__ int   g_col[MAX_E];
__device__ float g_w[MAX_E];

// ---------------- helpers -----------------------------------------------------
static __device__ __forceinline__ uint32_t smem_u32(const void* p) {
    uint32_t r;
    asm("{ .reg .u64 t; cvta.to.shared.u64 t, %1; cvt.u32.u64 %0, t; }"
        : "=r"(r) : "l"(p));
    return r;
}
static __device__ __forceinline__ void ldm_x4(uint32_t* r, uint32_t addr) {
    asm volatile("ldmatrix.sync.aligned.m8n8.x4.shared.b16 {%0,%1,%2,%3}, [%4];"
                 : "=r"(r[0]), "=r"(r[1]), "=r"(r[2]), "=r"(r[3]) : "r"(addr));
}
static __device__ __forceinline__ void mma16816(float* c, const uint32_t* a,
                                                uint32_t b0, uint32_t b1) {
    asm volatile("mma.sync.aligned.m16n8k16.row.col.f32.bf16.bf16.f32 "
                 "{%0,%1,%2,%3}, {%4,%5,%6,%7}, {%8,%9}, {%0,%1,%2,%3};"
                 : "+f"(c[0]), "+f"(c[1]), "+f"(c[2]), "+f"(c[3])
                 : "r"(a[0]), "r"(a[1]), "r"(a[2]), "r"(a[3]), "r"(b0), "r"(b1));
}
static __device__ __forceinline__ void cp16(uint32_t dst, const void* src, uint32_t sz) {
    asm volatile("cp.async.cg.shared.global [%0], [%1], 16, %2;"
                 :: "r"(dst), "l"(src), "r"(sz) : "memory");
}
#define CP_COMMIT()  asm volatile("cp.async.commit_group;" ::: "memory")
#define CP_WAIT(n)   asm volatile("cp.async.wait_group %0;" :: "n"(n) : "memory")

static __device__ __forceinline__ void split4(float4 v, uint2& hi, uint2& lo) {
    __nv_bfloat162 hxy = __floats2bfloat162_rn(v.x, v.y);
    __nv_bfloat162 hzw = __floats2bfloat162_rn(v.z, v.w);
    float lx = v.x - __bfloat162float(hxy.x), ly = v.y - __bfloat162float(hxy.y);
    float lz = v.z - __bfloat162float(hzw.x), lw = v.w - __bfloat162float(hzw.y);
    __nv_bfloat162 lxy = __floats2bfloat162_rn(lx, ly);
    __nv_bfloat162 lzw = __floats2bfloat162_rn(lz, lw);
    hi.x = *(uint32_t*)&hxy; hi.y = *(uint32_t*)&hzw;
    lo.x = *(uint32_t*)&lxy; lo.y = *(uint32_t*)&lzw;
}

// ---------------- index dtype detection + conversion ------------------------
__global__ void k_detect(const unsigned int* __restrict__ ei_words) {
    if (threadIdx.x == 0) {
        int nz = 0;
        for (int i = 0; i < 128; i++) nz += (ei_words[2 * i + 1] != 0u);
        g_is64 = (nz == 0) ? 1 : 0;
    }
}

__global__ void k_convert(const unsigned int* __restrict__ ei_words,
                          const unsigned int* __restrict__ batch_words, int E) {
    int t = blockIdx.x * blockDim.x + threadIdx.x;
    int is64 = g_is64;
    if (t < E) {
        if (is64) {
            g_src[t] = (int)ei_words[2 * t];
            g_dst[t] = (int)ei_words[2 * (E + t)];
        } else {
            g_src[t] = (int)ei_words[t];
            g_dst[t] = (int)ei_words[E + t];
        }
    }
    if (t < N_NODES) {
        g_batch[t] = is64 ? (int)batch_words[2 * t] : (int)batch_words[t];
    }
}

// ---------------- CSR build ---------------------------------------------------
__global__ void k_zero() {
    int t = blockIdx.x * blockDim.x + threadIdx.x;
    if (t < N_NODES) { g_degi[t] = 0; g_cursor[t] = 0; }
    if (t < NG * DH) g_pool[t] = 0.0f;
}

__global__ void k_count(int E) {
    int t = blockIdx.x * blockDim.x + threadIdx.x;
    if (t < E) atomicAdd(&g_degi[g_dst[t]], 1);
}

__global__ void k_graphcnt() {
    int b = threadIdx.x;
    if (b >= NG) return;
    auto lb = [&](int key) {
        int lo = 0, hi = N_NODES;
        while (lo < hi) { int m = (lo + hi) >> 1; if (g_batch[m] < key) lo = m + 1; else hi = m; }
        return lo;
    };
    g_cnt[b] = (float)(lb(b + 1) - lb(b));
}

__global__ void k_scan() {
    __shared__ int wsum[32];
    int tid = threadIdx.x, lane = tid & 31, wid = tid >> 5;
    int carry = 0;
    for (int base = 0; base < N_NODES; base += 1024) {
        int idx = base + tid;
        int v = (idx < N_NODES) ? g_degi[idx] : 0;
        int s = v;
        #pragma unroll
        for (int o = 1; o < 32; o <<= 1) {
            int t = __shfl_up_sync(0xffffffffu, s, o);
            if (lane >= o) s += t;
        }
        if (lane == 31) wsum[wid] = s;
        __syncthreads();
        if (wid == 0) {
            int ws = wsum[lane];
            #pragma unroll
            for (int o = 1; o < 32; o <<= 1) {
                int t = __shfl_up_sync(0xffffffffu, ws, o);
                if (lane >= o) ws += t;
            }
            wsum[lane] = ws;
        }
        __syncthreads();
        int prefix = (wid > 0) ? wsum[wid - 1] : 0;
        int total  = wsum[31];
        if (idx < N_NODES) {
            g_rowptr[idx] = carry + prefix + s - v;
            g_dinv[idx]   = rsqrtf((float)(v + 1));
        }
        carry += total;
        __syncthreads();
    }
    if (tid == 0) g_rowptr[N_NODES] = carry;
}

__global__ void k_fill(int E) {
    int e = blockIdx.x * blockDim.x + threadIdx.x;
    if (e >= E) return;
    int s = g_src[e], d = g_dst[e];
    int pos = g_rowptr[d] + atomicAdd(&g_cursor[d], 1);
    g_col[pos] = s;
    g_w[pos]   = g_dinv[s] * g_dinv[d];
}

// ---------------- weight splits ----------------------------------------------
__global__ void k_splitW_all(const float* __restrict__ W0,
                             const float* __restrict__ W1,
                             const float* __restrict__ W2) {
    int t = blockIdx.x * blockDim.x + threadIdx.x;
    const int T0 = 128 * DH, T12 = DH * DH;
    float v; int layer, idx;
    if (t < T0) {
        layer = 0; int k = t / DH, n = t % DH;
        v = W0[t]; idx = n * 128 + k;
    } else if (t < T0 + T12) {
        layer = 1; int u = t - T0; int k = u / DH, n = u % DH;
        v = W1[u]; idx = n * 256 + k;
    } else if (t < T0 + 2 * T12) {
        layer = 2; int u = t - T0 - T12; int k = u / DH, n = u % DH;
        v = W2[u]; idx = n * 256 + k;
    } else return;
    __nv_bfloat16 h = __float2bfloat16(v);
    g_Bh[layer][idx] = h;
    g_Bl[layer][idx] = __float2bfloat16(v - __bfloat162float(h));
}

// ---------------- layer-0 aggregation on x (128 dims) ------------------------
// one warp per node, each lane owns 4 features; writes bf16 splits to g_xh/g_xl
__global__ __launch_bounds__(256) void k_aggX(const float* __restrict__ x) {
    int node = (blockIdx.x * blockDim.x + threadIdx.x) >> 5;
    int lane = threadIdx.x & 31;
    if (node >= N_NODES) return;

    float s  = g_dinv[node];
    float s2 = s * s;
    float4 a = __ldg((const float4*)x + (size_t)node * 32 + lane);
    a.x *= s2; a.y *= s2; a.z *= s2; a.w *= s2;

    int beg = g_rowptr[node], end = g_rowptr[node + 1];
    int e = beg;
    for (; e + 1 < end; e += 2) {
        int   c0 = __ldg(&g_col[e]);
        int   c1 = __ldg(&g_col[e + 1]);
        float w0 = __ldg(&g_w[e]);
        float w1 = __ldg(&g_w[e + 1]);
        float4 v0 = __ldg((const float4*)x + (size_t)c0 * 32 + lane);
        float4 v1 = __ldg((const float4*)x + (size_t)c1 * 32 + lane);
        a.x += w0 * v0.x; a.y += w0 * v0.y; a.z += w0 * v0.z; a.w += w0 * v0.w;
        a.x += w1 * v1.x; a.y += w1 * v1.y; a.z += w1 * v1.z; a.w += w1 * v1.w;
    }
    if (e < end) {
        int   c = __ldg(&g_col[e]);
        float w = __ldg(&g_w[e]);
        float4 v = __ldg((const float4*)x + (size_t)c * 32 + lane);
        a.x += w * v.x; a.y += w * v.y; a.z += w * v.z; a.w += w * v.w;
    }

    uint2 hi, lo;
    split4(a, hi, lo);
    *(uint2*)(g_xh + (size_t)node * 128 + 4 * lane) = hi;
    *(uint2*)(g_xl + (size_t)node * 128 + 4 * lane) = lo;
}

// ---------------- aggregation on H (256 dims) --------------------------------
// one warp per node, reads fp32 g_H, writes bf16 splits to g_Mh/g_Ml
__global__ __launch_bounds__(256) void k_agg(void) {
    int node = (blockIdx.x * blockDim.x + threadIdx.x) >> 5;
    int lane = threadIdx.x & 31;
    if (node >= N_NODES) return;

    const float4* Hi = (const float4*)g_H + (size_t)node * DH4;
    float s  = g_dinv[node];
    float s2 = s * s;

    float4 a0 = __ldg(Hi + lane);
    float4 a1 = __ldg(Hi + lane + 32);
    a0.x *= s2; a0.y *= s2; a0.z *= s2; a0.w *= s2;
    a1.x *= s2; a1.y *= s2; a1.z *= s2; a1.w *= s2;

    int beg = g_rowptr[node], end = g_rowptr[node + 1];
    int e = beg;
    for (; e + 1 < end; e += 2) {
        int   c0 = __ldg(&g_col[e]);
        int   c1 = __ldg(&g_col[e + 1]);
        float w0 = __ldg(&g_w[e]);
        float w1 = __ldg(&g_w[e + 1]);
        const float4* H0 = (const float4*)g_H + (size_t)c0 * DH4;
        const float4* H1 = (const float4*)g_H + (size_t)c1 * DH4;
        float4 v00 = __ldg(H0 + lane);
        float4 v01 = __ldg(H0 + lane + 32);
        float4 v10 = __ldg(H1 + lane);
        float4 v11 = __ldg(H1 + lane + 32);
        a0.x += w0 * v00.x; a0.y += w0 * v00.y; a0.z += w0 * v00.z; a0.w += w0 * v00.w;
        a1.x += w0 * v01.x; a1.y += w0 * v01.y; a1.z += w0 * v01.z; a1.w += w0 * v01.w;
        a0.x += w1 * v10.x; a0.y += w1 * v10.y; a0.z += w1 * v10.z; a0.w += w1 * v10.w;
        a1.x += w1 * v11.x; a1.y += w1 * v11.y; a1.z += w1 * v11.z; a1.w += w1 * v11.w;
    }
    if (e < end) {
        int   c = __ldg(&g_col[e]);
        float w = __ldg(&g_w[e]);
        const float4* Hs = (const float4*)g_H + (size_t)c * DH4;
        float4 v0 = __ldg(Hs + lane);
        float4 v1 = __ldg(Hs + lane + 32);
        a0.x += w * v0.x; a0.y += w * v0.y; a0.z += w * v0.z; a0.w += w * v0.w;
        a1.x += w * v1.x; a1.y += w * v1.y; a1.z += w * v1.z; a1.w += w * v1.w;
    }

    uint2 h0, l0, h1, l1;
    split4(a0, h0, l0);
    split4(a1, h1, l1);
    *(uint2*)(g_Mh + (size_t)node * DH + 4 * lane)        = h0;
    *(uint2*)(g_Ml + (size_t)node * DH + 4 * lane)        = l0;
    *(uint2*)(g_Mh + (size_t)node * DH + 4 * (lane + 32)) = h1;
    *(uint2*)(g_Ml + (size_t)node * DH + 4 * (lane + 32)) = l1;
}

// ---------------- split-bf16 HMMA GEMM, 2-stage cp.async pipeline -------------
// epilogue mode 0: H = relu(acc + bias) -> g_H fp32
// epilogue mode 1: relu(acc + bias) -> smem staging -> pooled atomics (final)
#define KC       32
#define ASTRIDE  40
#define BUF_ELEM (128 * ASTRIDE)
#define BUF_B    (BUF_ELEM * 2)
#define MMA_SMEM (2 * 4 * BUF_B)          // 81920 B
#define PSTRIDE  132                      // fp32 stage stride (mode 1)

__global__ __launch_bounds__(256) void k_mma(int K, int useX, int layer,
                                             const float* __restrict__ bias,
                                             int mode) {
    extern __shared__ __nv_bfloat16 dsm[];
    __shared__ int sbatch[128];
    const __nv_bfloat16* __restrict__ Ah = useX ? g_xh : g_Mh;
    const __nv_bfloat16* __restrict__ Al = useX ? g_xl : g_Ml;
    const __nv_bfloat16* __restrict__ Bh = g_Bh[layer];
    const __nv_bfloat16* __restrict__ Bl = g_Bl[layer];

    const int tid = threadIdx.x, wid = tid >> 5, lane = tid & 31;
    const int warpRow = wid >> 1, warpCol = wid & 1;
    const int cCol = blockIdx.x;
    const int rowBase = blockIdx.y * 128;
    const uint32_t sb = smem_u32(dsm);

    const int ldRow = tid >> 1;
    const int grow  = rowBase + ldRow;
    const uint32_t asz = (grow < N_NODES) ? 16u : 0u;
    const size_t aOff = (size_t)(grow < N_NODES ? grow : 0) * K;
    const size_t bOff = (size_t)(cCol * 128 + ldRow) * K;
    const uint32_t dRowB = (uint32_t)ldRow * (ASTRIDE * 2);

    const int nC = K / KC;

    auto issue = [&](int c, int s) {
        const int k0 = c * KC;
        const uint32_t base = sb + (uint32_t)(s * 4) * BUF_B + dRowB;
        #pragma unroll
        for (int q = 0; q < 2; q++) {
            const int col8 = ((tid & 1) * 2 + q) * 8;
            const uint32_t d = base + col8 * 2;
            cp16(d,             Ah + aOff + k0 + col8, asz);
            cp16(d + BUF_B,     Al + aOff + k0 + col8, asz);
            cp16(d + 2 * BUF_B, Bh + bOff + k0 + col8, 16u);
            cp16(d + 3 * BUF_B, Bl + bOff + k0 + col8, 16u);
        }
        CP_COMMIT();
    };

    float acc[2][8][4];
    #pragma unroll
    for (int mi = 0; mi < 2; mi++)
        #pragma unroll
        for (int ni = 0; ni < 8; ni++)
            #pragma unroll
            for (int q = 0; q < 4; q++) acc[mi][ni][q] = 0.0f;

    issue(0, 0);
    issue(1, 1);

    for (int c = 0; c < nC; c++) {
        const int s = c & 1;
        if (c + 1 < nC) CP_WAIT(1); else CP_WAIT(0);
        __syncthreads();

        const __nv_bfloat16* sAh = dsm + (s * 4 + 0) * BUF_ELEM;
        const __nv_bfloat16* sAl = dsm + (s * 4 + 1) * BUF_ELEM;
        const __nv_bfloat16* sBh = dsm + (s * 4 + 2) * BUF_ELEM;
        const __nv_bfloat16* sBl = dsm + (s * 4 + 3) * BUF_ELEM;

        #pragma unroll
        for (int ks = 0; ks < 2; ks++) {
            uint32_t ah[2][4], al[2][4];
            #pragma unroll
            for (int mi = 0; mi < 2; mi++) {
                int r = warpRow * 32 + mi * 16 + (lane & 15);
                int cc = ks * 16 + (lane >> 4) * 8;
                ldm_x4(ah[mi], smem_u32(sAh + r * ASTRIDE + cc));
                ldm_x4(al[mi], smem_u32(sAl + r * ASTRIDE + cc));
            }
            uint32_t bh[4][4], bl[4][4];
            #pragma unroll
            for (int nj = 0; nj < 4; nj++) {
                int n = warpCol * 64 + nj * 16 + (lane & 7) + ((lane >> 3) & 1) * 8;
                int cc = ks * 16 + (lane >> 4) * 8;
                ldm_x4(bh[nj], smem_u32(sBh + n * ASTRIDE + cc));
                ldm_x4(bl[nj], smem_u32(sBl + n * ASTRIDE + cc));
            }
            #pragma unroll
            for (int mi = 0; mi < 2; mi++) {
                #pragma unroll
                for (int nj = 0; nj < 4; nj++) {
                    mma16816(acc[mi][nj * 2],     ah[mi], bh[nj][0], bh[nj][2]);
                    mma16816(acc[mi][nj * 2 + 1], ah[mi], bh[nj][1], bh[nj][3]);
                    mma16816(acc[mi][nj * 2],     ah[mi], bl[nj][0], bl[nj][2]);
                    mma16816(acc[mi][nj * 2 + 1], ah[mi], bl[nj][1], bl[nj][3]);
                    mma16816(acc[mi][nj * 2],     al[mi], bh[nj][0], bh[nj][2]);
                    mma16816(acc[mi][nj * 2 + 1], al[mi], bh[nj][1], bh[nj][3]);
                }
            }
        }
        __syncthreads();
        if (c + 2 < nC) issue(c + 2, s);
    }

    if (mode == 0) {
        #pragma unroll
        for (int mi = 0; mi < 2; mi++) {
            int r0 = rowBase + warpRow * 32 + mi * 16 + (lane >> 2);
            #pragma unroll
            for (int ni = 0; ni < 8; ni++) {
                int col = cCol * 128 + warpCol * 64 + ni * 8 + (lane & 3) * 2;
                float bx = __ldg(bias + col), by = __ldg(bias + col + 1);
                float2 v0 = make_float2(fmaxf(acc[mi][ni][0] + bx, 0.f),
                                        fmaxf(acc[mi][ni][1] + by, 0.f));
                float2 v1 = make_float2(fmaxf(acc[mi][ni][2] + bx, 0.f),
                                        fmaxf(acc[mi][ni][3] + by, 0.f));
                if (r0 < N_NODES)
                    *(float2*)(g_H + (size_t)r0 * DH + col) = v0;
                if (r0 + 8 < N_NODES)
                    *(float2*)(g_H + (size_t)(r0 + 8) * DH + col) = v1;
            }
        }
    } else {
        // final layer: stage relu(acc+bias) in smem, pool by batch id
        float* sp = (float*)dsm;   // [128][PSTRIDE]
        #pragma unroll
        for (int mi = 0; mi < 2; mi++) {
            int rl = warpRow * 32 + mi * 16 + (lane >> 2);
            #pragma unroll
            for (int ni = 0; ni < 8; ni++) {
                int cl  = warpCol * 64 + ni * 8 + (lane & 3) * 2;
                int col = cCol * 128 + cl;
                float bx = __ldg(bias + col), by = __ldg(bias + col + 1);
                sp[rl * PSTRIDE + cl]           = fmaxf(acc[mi][ni][0] + bx, 0.f);
                sp[rl * PSTRIDE + cl + 1]       = fmaxf(acc[mi][ni][1] + by, 0.f);
                sp[(rl + 8) * PSTRIDE + cl]     = fmaxf(acc[mi][ni][2] + bx, 0.f);
                sp[(rl + 8) * PSTRIDE + cl + 1] = fmaxf(acc[mi][ni][3] + by, 0.f);
            }
        }
        if (tid < 128) {
            int gr = rowBase + tid;
            sbatch[tid] = (gr < N_NODES) ? g_batch[gr] : -1;
        }
        __syncthreads();

        int col  = tid & 127;
        int half = tid >> 7;
        float a = 0.0f;
        int cb = -1;
        for (int r = half * 64; r < half * 64 + 64; r++) {
            int b = sbatch[r];
            if (b != cb) {
                if (cb >= 0) atomicAdd(&g_pool[cb * DH + cCol * 128 + col], a);
                a = 0.0f; cb = b;
            }
            if (b >= 0) a += sp[r * PSTRIDE + col];
        }
        if (cb >= 0) atomicAdd(&g_pool[cb * DH + cCol * 128 + col], a);
    }
}

// ---------------- classifier head ------------------------------------------
__global__ void k_classifier(const float* __restrict__ Wc1, const float* __restrict__ bc1,
                             const float* __restrict__ Wc2, const float* __restrict__ bc2,
                             float* __restrict__ out) {
    __shared__ float gr[DH];
    __shared__ float h1[DH];
    int b = blockIdx.x, tid = threadIdx.x;

    float invc = 1.0f / fmaxf(g_cnt[b], 1.0f);
    gr[tid] = g_pool[b * DH + tid] * invc;
    __syncthreads();

    float acc = bc1[tid];
    #pragma unroll 8
    for (int k = 0; k < DH; k++) acc += gr[k] * Wc1[k * DH + tid];
    h1[tid] = fmaxf(acc, 0.f);
    __syncthreads();

    if (tid < 5) {
        float o = bc2[tid];
        #pragma unroll 8
        for (int k = 0; k < DH; k++) o += h1[k] * Wc2[k * 5 + tid];
        out[b * 5 + tid] = o;
    }
}

// ---------------- launch ------------------------------------------------------
extern "C" void kernel_launch(void* const* d_in, const int* in_sizes, int n_in,
                              void* d_out, int out_size) {
    const float*        x     = (const float*)d_in[0];
    const unsigned int* ei    = (const unsigned int*)d_in[1];
    const unsigned int* batch = (const unsigned int*)d_in[2];
    const float* W0  = (const float*)d_in[3];
    const float* b0  = (const float*)d_in[4];
    const float* W1  = (const float*)d_in[5];
    const float* b1  = (const float*)d_in[6];
    const float* W2  = (const float*)d_in[7];
    const float* b2  = (const float*)d_in[8];
    const float* Wc1 = (const float*)d_in[9];
    const float* bc1 = (const float*)d_in[10];
    const float* Wc2 = (const float*)d_in[11];
    const float* bc2 = (const float*)d_in[12];
    float* out = (float*)d_out;

    const int E = in_sizes[1] / 2;

    cudaFuncSetAttribute(k_mma, cudaFuncAttributeMaxDynamicSharedMemorySize, MMA_SMEM);

    // prep
    k_detect<<<1, 32>>>(ei);
    k_convert<<<(E + 255) / 256, 256>>>(ei, batch, E);
    k_zero<<<(N_NODES + 255) / 256, 256>>>();
    k_count<<<(E + 255) / 256, 256>>>(E);
    k_graphcnt<<<1, 64>>>();
    k_scan<<<1, 1024>>>();
    k_fill<<<(E + 255) / 256, 256>>>(E);
    k_splitW_all<<<(128 * DH + 2 * DH * DH + 255) / 256, 256>>>(W0, W1, W2);

    const dim3 ggrid(2, (N_NODES + 127) / 128);
    const int  aggBlocks = (N_NODES * 32 + 255) / 256;

    // layer 0: M0 = Agg(x) [128d], H1 = relu(M0@W0 + b0)
    k_aggX<<<aggBlocks, 256>>>(x);
    k_mma<<<ggrid, 256, MMA_SMEM>>>(128, 1, 0, b0, 0);

    // layer 1: M1 = Agg(H1), H2 = relu(M1@W1 + b1)
    k_agg<<<aggBlocks, 256>>>();
    k_mma<<<ggrid, 256, MMA_SMEM>>>(256, 0, 1, b1, 0);

    // layer 2: M2 = Agg(H2), pool(relu(M2@W2 + b2)) fused in epilogue
    k_agg<<<aggBlocks, 256>>>();
    k_mma<<<ggrid, 256, MMA_SMEM>>>(256, 0, 2, b2, 1);

    // classifier
    k_classifier<<<NG, DH>>>(Wc1, bc1, Wc2, bc2, out);
}